// round 11
// baseline (speedup 1.0000x reference)
#include <cuda_runtime.h>
#include <math.h>

#define S 2048
#define D 512
#define H 8
#define DH 64
#define L 4
#define FF 2048
#define NC (S / 64)          // 32 chunks of 64

typedef unsigned long long ull;

// ---------------- scratch (static device globals; no allocation) ----------------
__device__ float d_x  [S * D];
__device__ float d_y  [S * D];
__device__ float d_q  [S * D];
__device__ float d_k  [S * D];
__device__ float d_v  [S * D];
__device__ float d_g  [S * D];
__device__ float d_ret[S * D];
__device__ float d_ff [S * FF];
__device__ float d_sin[S * (DH / 2)];
__device__ float d_cos[S * (DH / 2)];
__device__ float d_gpow[H * S];
__device__ float d_U[H * NC * DH * DH];   // per-chunk decayed k^T v
__device__ float d_M[H * NC * DH * DH];   // prefix states

// ---------------- f32x2 helpers ----------------
__device__ __forceinline__ ull dup2(float x) {
    ull r; asm("mov.b64 %0, {%1, %1};" : "=l"(r) : "f"(x)); return r;
}
__device__ __forceinline__ void ff2(ull& d, ull a, ull b) {
    asm("fma.rn.f32x2 %0, %1, %2, %0;" : "+l"(d) : "l"(a), "l"(b));
}
__device__ __forceinline__ float2 unpack2(ull p) {
    float2 r; asm("mov.b64 {%0, %1}, %2;" : "=f"(r.x), "=f"(r.y) : "l"(p)); return r;
}

// ---------------- setup tables (double precision, matches numpy float64) --------
__global__ void init_tables_kernel() {
    int idx = blockIdx.x * blockDim.x + threadIdx.x;
    if (idx < S * (DH / 2)) {
        int s = idx / (DH / 2);
        int j = idx % (DH / 2);
        double theta = pow(10000.0, -(double)(2 * j) / (double)DH);
        double ang = (double)s * theta;
        d_sin[idx] = (float)sin(ang);
        d_cos[idx] = (float)cos(ang);
    }
    if (idx < H * S) {
        int h = idx / S;
        int dd = idx % S;
        double lg0 = log(1.0 / 32.0);
        double lg1 = log(1.0 / 512.0);
        double gamma = 1.0 - exp(lg0 + (lg1 - lg0) * (double)h / 7.0);
        d_gpow[idx] = (float)exp((double)dd * log(gamma));
    }
}

__global__ void add_pos_kernel(const float* __restrict__ x, const float* __restrict__ pe) {
    int i = blockIdx.x * blockDim.x + threadIdx.x;
    if (i < S * D) d_x[i] = x[i] + pe[i % D];
}

// ---------------- layernorm ----------------
__global__ void layernorm_kernel(const float* __restrict__ in,
                                 const float* __restrict__ w,
                                 const float* __restrict__ b,
                                 float* __restrict__ out, float eps) {
    int row = blockIdx.x;
    int t = threadIdx.x;
    const float* xr = in + row * D;
    __shared__ float red[256];

    float v0 = xr[t];
    float v1 = xr[t + 256];
    red[t] = v0 + v1;
    __syncthreads();
    for (int o = 128; o > 0; o >>= 1) {
        if (t < o) red[t] += red[t + o];
        __syncthreads();
    }
    float mu = red[0] * (1.0f / D);
    __syncthreads();
    float a0 = v0 - mu, a1 = v1 - mu;
    red[t] = a0 * a0 + a1 * a1;
    __syncthreads();
    for (int o = 128; o > 0; o >>= 1) {
        if (t < o) red[t] += red[t + o];
        __syncthreads();
    }
    float rstd = rsqrtf(red[0] * (1.0f / D) + eps);
    out[row * D + t]       = a0 * rstd * w[t]       + b[t];
    out[row * D + t + 256] = a1 * rstd * w[t + 256] + b[t + 256];
}

// ================= f32x2 GEMM core: BM=128, BN=128, BK=16, 256 thr ==============
// Warp tiling: 8 warps as 4x2 (32 rows x 64 cols each); lanes 4x8 (8 rows x 8 cols).
// Double-buffered smem, one sync per k-tile.
template <int N, int K>
__device__ __forceinline__ void gemm128_accum(const float* __restrict__ A,
                                              const float* __restrict__ W,
                                              float (*As)[16][132], float (*Bs)[16][128],
                                              ull (&acc)[8][4]) {
    const int tid = threadIdx.x;
    const int row0 = blockIdx.y * 128;
    const int col0 = blockIdx.x * 128;
    const int arow = tid >> 1, ac8 = (tid & 1) * 8;
    const int brow = tid >> 4, bcol = (tid & 15) * 8;
    const int warp = tid >> 5, lane = tid & 31;
    const int ro = (warp >> 1) * 32 + (lane >> 3) * 8;
    const int co = (warp & 1) * 64 + (lane & 7) * 8;

    const float* Ap = A + (row0 + arow) * K + ac8;
    const float* Wp = W + brow * N + col0 + bcol;

    float4 fa0 = *(const float4*)Ap;
    float4 fa1 = *(const float4*)(Ap + 4);
    float4 fb0 = *(const float4*)Wp;
    float4 fb1 = *(const float4*)(Wp + 4);

    int buf = 0;
    As[0][ac8 + 0][arow] = fa0.x; As[0][ac8 + 1][arow] = fa0.y;
    As[0][ac8 + 2][arow] = fa0.z; As[0][ac8 + 3][arow] = fa0.w;
    As[0][ac8 + 4][arow] = fa1.x; As[0][ac8 + 5][arow] = fa1.y;
    As[0][ac8 + 6][arow] = fa1.z; As[0][ac8 + 7][arow] = fa1.w;
    *(float4*)&Bs[0][brow][bcol]     = fb0;
    *(float4*)&Bs[0][brow][bcol + 4] = fb1;
    __syncthreads();

    for (int k0 = 0; k0 < K; k0 += 16) {
        bool more = (k0 + 16 < K);
        if (more) {
            fa0 = *(const float4*)(Ap + k0 + 16);
            fa1 = *(const float4*)(Ap + k0 + 20);
            fb0 = *(const float4*)(Wp + (k0 + 16) * N);
            fb1 = *(const float4*)(Wp + (k0 + 16) * N + 4);
        }
#pragma unroll
        for (int kk = 0; kk < 16; kk++) {
            float4 alo = *(const float4*)&As[buf][kk][ro];
            float4 ahi = *(const float4*)&As[buf][kk][ro + 4];
            ulonglong2 bA = *(const ulonglong2*)&Bs[buf][kk][co];
            ulonglong2 bB = *(const ulonglong2*)&Bs[buf][kk][co + 4];
            ull a2;
            a2 = dup2(alo.x); ff2(acc[0][0], a2, bA.x); ff2(acc[0][1], a2, bA.y); ff2(acc[0][2], a2, bB.x); ff2(acc[0][3], a2, bB.y);
            a2 = dup2(alo.y); ff2(acc[1][0], a2, bA.x); ff2(acc[1][1], a2, bA.y); ff2(acc[1][2], a2, bB.x); ff2(acc[1][3], a2, bB.y);
            a2 = dup2(alo.z); ff2(acc[2][0], a2, bA.x); ff2(acc[2][1], a2, bA.y); ff2(acc[2][2], a2, bB.x); ff2(acc[2][3], a2, bB.y);
            a2 = dup2(alo.w); ff2(acc[3][0], a2, bA.x); ff2(acc[3][1], a2, bA.y); ff2(acc[3][2], a2, bB.x); ff2(acc[3][3], a2, bB.y);
            a2 = dup2(ahi.x); ff2(acc[4][0], a2, bA.x); ff2(acc[4][1], a2, bA.y); ff2(acc[4][2], a2, bB.x); ff2(acc[4][3], a2, bB.y);
            a2 = dup2(ahi.y); ff2(acc[5][0], a2, bA.x); ff2(acc[5][1], a2, bA.y); ff2(acc[5][2], a2, bB.x); ff2(acc[5][3], a2, bB.y);
            a2 = dup2(ahi.z); ff2(acc[6][0], a2, bA.x); ff2(acc[6][1], a2, bA.y); ff2(acc[6][2], a2, bB.x); ff2(acc[6][3], a2, bB.y);
            a2 = dup2(ahi.w); ff2(acc[7][0], a2, bA.x); ff2(acc[7][1], a2, bA.y); ff2(acc[7][2], a2, bB.x); ff2(acc[7][3], a2, bB.y);
        }
        if (more) {
            int nb = buf ^ 1;
            As[nb][ac8 + 0][arow] = fa0.x; As[nb][ac8 + 1][arow] = fa0.y;
            As[nb][ac8 + 2][arow] = fa0.z; As[nb][ac8 + 3][arow] = fa0.w;
            As[nb][ac8 + 4][arow] = fa1.x; As[nb][ac8 + 5][arow] = fa1.y;
            As[nb][ac8 + 6][arow] = fa1.z; As[nb][ac8 + 7][arow] = fa1.w;
            *(float4*)&Bs[nb][brow][bcol]     = fb0;
            *(float4*)&Bs[nb][brow][bcol + 4] = fb1;
            __syncthreads();
            buf = nb;
        }
    }
}

// ---- quad projection GEMM: z=0:q(rope*0.125) 1:k(rope) 2:v 3:g(silu) ----
__global__ void __launch_bounds__(256, 2) qkvg_gemm(
    const float* __restrict__ A,
    const float* __restrict__ Wq_, const float* __restrict__ Wk_,
    const float* __restrict__ Wv_, const float* __restrict__ Wg_,
    const float* __restrict__ bq_, const float* __restrict__ bk_,
    const float* __restrict__ bv_, const float* __restrict__ bg_) {
    __shared__ float As[2][16][132];
    __shared__ float Bs[2][16][128];
    int z = blockIdx.z;
    const float* W    = (z == 0) ? Wq_ : (z == 1) ? Wk_ : (z == 2) ? Wv_ : Wg_;
    const float* bias = (z == 0) ? bq_ : (z == 1) ? bk_ : (z == 2) ? bv_ : bg_;
    float* out        = (z == 0) ? d_q : (z == 1) ? d_k : (z == 2) ? d_v : d_g;

    ull acc[8][4];
#pragma unroll
    for (int r = 0; r < 8; r++)
#pragma unroll
        for (int c = 0; c < 4; c++) acc[r][c] = 0ull;

    gemm128_accum<D, D>(A, W, As, Bs, acc);

    const int tid = threadIdx.x;
    const int warp = tid >> 5, lane = tid & 31;
    const int ro = (warp >> 1) * 32 + (lane >> 3) * 8;
    const int co = (warp & 1) * 64 + (lane & 7) * 8;
    const int row0 = blockIdx.y * 128, col0 = blockIdx.x * 128;
#pragma unroll
    for (int r = 0; r < 8; r++) {
        int row = row0 + ro + r;
#pragma unroll
        for (int half = 0; half < 2; half++) {
            int col = col0 + co + 4 * half;
            float2 p0 = unpack2(acc[r][2 * half]);
            float2 p1 = unpack2(acc[r][2 * half + 1]);
            float v0 = p0.x + bias[col];
            float v1 = p0.y + bias[col + 1];
            float v2 = p1.x + bias[col + 2];
            float v3 = p1.y + bias[col + 3];
            float4 o;
            if (z <= 1) {
                int j = (col & 63) >> 1;
                float c0 = d_cos[row * 32 + j],     s0 = d_sin[row * 32 + j];
                float c1 = d_cos[row * 32 + j + 1], s1 = d_sin[row * 32 + j + 1];
                float sc = (z == 0) ? 0.125f : 1.0f;
                o.x = (v0 * c0 - v1 * s0) * sc;
                o.y = (v1 * c0 + v0 * s0) * sc;
                o.z = (v2 * c1 - v3 * s1) * sc;
                o.w = (v3 * c1 + v2 * s1) * sc;
            } else if (z == 2) {
                o = make_float4(v0, v1, v2, v3);
            } else {
                o.x = v0 / (1.0f + expf(-v0));
                o.y = v1 / (1.0f + expf(-v1));
                o.z = v2 / (1.0f + expf(-v2));
                o.w = v3 / (1.0f + expf(-v3));
            }
            *(float4*)&out[row * D + col] = o;
        }
    }
}

// ---- FFN1 GEMM with SiLU: [S,512]@[512,2048] ----
__global__ void __launch_bounds__(256, 2) ffn1_gemm(
    const float* __restrict__ A, const float* __restrict__ W,
    const float* __restrict__ bias) {
    __shared__ float As[2][16][132];
    __shared__ float Bs[2][16][128];
    ull acc[8][4];
#pragma unroll
    for (int r = 0; r < 8; r++)
#pragma unroll
        for (int c = 0; c < 4; c++) acc[r][c] = 0ull;

    gemm128_accum<FF, D>(A, W, As, Bs, acc);

    const int tid = threadIdx.x;
    const int warp = tid >> 5, lane = tid & 31;
    const int ro = (warp >> 1) * 32 + (lane >> 3) * 8;
    const int co = (warp & 1) * 64 + (lane & 7) * 8;
    const int row0 = blockIdx.y * 128, col0 = blockIdx.x * 128;
#pragma unroll
    for (int r = 0; r < 8; r++) {
        int row = row0 + ro + r;
#pragma unroll
        for (int half = 0; half < 2; half++) {
            int col = col0 + co + 4 * half;
            float2 p0 = unpack2(acc[r][2 * half]);
            float2 p1 = unpack2(acc[r][2 * half + 1]);
            float v0 = p0.x + bias[col];
            float v1 = p0.y + bias[col + 1];
            float v2 = p1.x + bias[col + 2];
            float v3 = p1.y + bias[col + 3];
            float4 o;
            o.x = v0 / (1.0f + expf(-v0));
            o.y = v1 / (1.0f + expf(-v1));
            o.z = v2 / (1.0f + expf(-v2));
            o.w = v3 / (1.0f + expf(-v3));
            *(float4*)&d_ff[row * FF + col] = o;
        }
    }
}

// ---- BM=64 BN=128 residual GEMM (N=512): C += A(*A2)@W + bias ----
// Warp tiling: 8 warps as 2x4 (32 rows x 32 cols); lanes 8x4 (4 rows x 8 cols).
template <int K, bool MULA>
__global__ void __launch_bounds__(256, 2) gemm64_res(
    const float* __restrict__ A, const float* __restrict__ A2,
    const float* __restrict__ W, const float* __restrict__ bias,
    float* __restrict__ C) {
    __shared__ float As[2][16][68];
    __shared__ float Bs[2][16][128];
    const int tid = threadIdx.x;
    const int row0 = blockIdx.y * 64;
    const int col0 = blockIdx.x * 128;
    const int arow = tid >> 2, ac4 = (tid & 3) * 4;
    const int brow = tid >> 4, bcol = (tid & 15) * 8;
    const int warp = tid >> 5, lane = tid & 31;
    const int ro = (warp >> 2) * 32 + (lane >> 2) * 4;
    const int co = (warp & 3) * 32 + (lane & 3) * 8;

    const float* Ap  = A  + (row0 + arow) * K + ac4;
    const float* A2p = A2 + (row0 + arow) * K + ac4;
    const float* Wp  = W + brow * 512 + col0 + bcol;

    float4 fa = *(const float4*)Ap;
    if (MULA) {
        float4 fm = *(const float4*)A2p;
        fa.x *= fm.x; fa.y *= fm.y; fa.z *= fm.z; fa.w *= fm.w;
    }
    float4 fb0 = *(const float4*)Wp;
    float4 fb1 = *(const float4*)(Wp + 4);

    ull acc[4][4];
#pragma unroll
    for (int r = 0; r < 4; r++)
#pragma unroll
        for (int c = 0; c < 4; c++) acc[r][c] = 0ull;

    int buf = 0;
    As[0][ac4 + 0][arow] = fa.x; As[0][ac4 + 1][arow] = fa.y;
    As[0][ac4 + 2][arow] = fa.z; As[0][ac4 + 3][arow] = fa.w;
    *(float4*)&Bs[0][brow][bcol]     = fb0;
    *(float4*)&Bs[0][brow][bcol + 4] = fb1;
    __syncthreads();

    for (int k0 = 0; k0 < K; k0 += 16) {
        bool more = (k0 + 16 < K);
        if (more) {
            fa = *(const float4*)(Ap + k0 + 16);
            if (MULA) {
                float4 fm = *(const float4*)(A2p + k0 + 16);
                fa.x *= fm.x; fa.y *= fm.y; fa.z *= fm.z; fa.w *= fm.w;
            }
            fb0 = *(const float4*)(Wp + (k0 + 16) * 512);
            fb1 = *(const float4*)(Wp + (k0 + 16) * 512 + 4);
        }
#pragma unroll
        for (int kk = 0; kk < 16; kk++) {
            float4 av = *(const float4*)&As[buf][kk][ro];
            ulonglong2 bA = *(const ulonglong2*)&Bs[buf][kk][co];
            ulonglong2 bB = *(const ulonglong2*)&Bs[buf][kk][co + 4];
            ull a2;
            a2 = dup2(av.x); ff2(acc[0][0], a2, bA.x); ff2(acc[0][1], a2, bA.y); ff2(acc[0][2], a2, bB.x); ff2(acc[0][3], a2, bB.y);
            a2 = dup2(av.y); ff2(acc[1][0], a2, bA.x); ff2(acc[1][1], a2, bA.y); ff2(acc[1][2], a2, bB.x); ff2(acc[1][3], a2, bB.y);
            a2 = dup2(av.z); ff2(acc[2][0], a2, bA.x); ff2(acc[2][1], a2, bA.y); ff2(acc[2][2], a2, bB.x); ff2(acc[2][3], a2, bB.y);
            a2 = dup2(av.w); ff2(acc[3][0], a2, bA.x); ff2(acc[3][1], a2, bA.y); ff2(acc[3][2], a2, bB.x); ff2(acc[3][3], a2, bB.y);
        }
        if (more) {
            int nb = buf ^ 1;
            As[nb][ac4 + 0][arow] = fa.x; As[nb][ac4 + 1][arow] = fa.y;
            As[nb][ac4 + 2][arow] = fa.z; As[nb][ac4 + 3][arow] = fa.w;
            *(float4*)&Bs[nb][brow][bcol]     = fb0;
            *(float4*)&Bs[nb][brow][bcol + 4] = fb1;
            __syncthreads();
            buf = nb;
        }
    }

#pragma unroll
    for (int r = 0; r < 4; r++) {
        int row = row0 + ro + r;
#pragma unroll
        for (int half = 0; half < 2; half++) {
            int col = col0 + co + 4 * half;
            float2 p0 = unpack2(acc[r][2 * half]);
            float2 p1 = unpack2(acc[r][2 * half + 1]);
            float4 oldv = *(float4*)&C[row * 512 + col];
            float4 o;
            o.x = p0.x + bias[col]     + oldv.x;
            o.y = p0.y + bias[col + 1] + oldv.y;
            o.z = p1.x + bias[col + 2] + oldv.z;
            o.w = p1.y + bias[col + 3] + oldv.w;
            *(float4*)&C[row * 512 + col] = o;
        }
    }
}

// ================= chunked retention =================
// R1: U[h][c] = sum_p gamma^(63-p) k_p (outer) v_p   (64x64 per chunk)
__global__ void chunk_kv_kernel(const float* __restrict__ k, const float* __restrict__ v) {
    __shared__ float ks[64][68];
    __shared__ float vs[64][68];
    int c = blockIdx.x, h = blockIdx.y;
    int s0 = c * 64;
    int tid = threadIdx.x;
    const float* gp = d_gpow + h * S;

    for (int i = tid; i < 64 * 16; i += 256) {
        int r = i >> 4;
        int c4 = (i & 15) * 4;
        float g = gp[63 - r];
        float4 kv = *(const float4*)&k[(s0 + r) * D + h * DH + c4];
        ks[r][c4 + 0] = kv.x * g; ks[r][c4 + 1] = kv.y * g;
        ks[r][c4 + 2] = kv.z * g; ks[r][c4 + 3] = kv.w * g;
        float4 vv = *(const float4*)&v[(s0 + r) * D + h * DH + c4];
        vs[r][c4 + 0] = vv.x; vs[r][c4 + 1] = vv.y;
        vs[r][c4 + 2] = vv.z; vs[r][c4 + 3] = vv.w;
    }
    __syncthreads();

    int tx = tid & 15, ty = tid >> 4;
    float acc[4][4] = {};
#pragma unroll 8
    for (int p = 0; p < 64; p++) {
        float4 a = *(const float4*)&ks[p][ty * 4];
        float4 b = *(const float4*)&vs[p][tx * 4];
        acc[0][0] += a.x * b.x; acc[0][1] += a.x * b.y; acc[0][2] += a.x * b.z; acc[0][3] += a.x * b.w;
        acc[1][0] += a.y * b.x; acc[1][1] += a.y * b.y; acc[1][2] += a.y * b.z; acc[1][3] += a.y * b.w;
        acc[2][0] += a.z * b.x; acc[2][1] += a.z * b.y; acc[2][2] += a.z * b.z; acc[2][3] += a.z * b.w;
        acc[3][0] += a.w * b.x; acc[3][1] += a.w * b.y; acc[3][2] += a.w * b.z; acc[3][3] += a.w * b.w;
    }
    float* U = d_U + (h * NC + c) * (DH * DH);
#pragma unroll
    for (int r = 0; r < 4; r++)
        *(float4*)&U[(ty * 4 + r) * DH + tx * 4] = make_float4(acc[r][0], acc[r][1], acc[r][2], acc[r][3]);
}

// R2: parallel-over-elements scan over chunks: M[c] = gamma^64 * M[c-1] + U[c-1]
__global__ void scan_kernel() {
    int e = blockIdx.x * blockDim.x + threadIdx.x;   // H*4096
    if (e >= H * DH * DH) return;
    int h = e >> 12;
    int idx = e & 4095;
    float gc = d_gpow[h * S + 64];
    float m = 0.0f;
    for (int c = 0; c < NC; c++) {
        d_M[(h * NC + c) * 4096 + idx] = m;
        m = gc * m + d_U[(h * NC + c) * 4096 + idx];
    }
}

// R3: intra-chunk masked attention + cross term + groupnorm
__global__ void retn_kernel(const float* __restrict__ q, const float* __restrict__ k,
                            const float* __restrict__ v, float* __restrict__ ret) {
    __shared__ float qs[64][65];
    __shared__ float ks[32][65];
    __shared__ float vs[32][65];
    __shared__ float ss[64][33];

    int h = blockIdx.y;
    int cidx = blockIdx.x;
    int s0 = cidx * 64;
    int tid = threadIdx.x;

    for (int i = tid; i < 64 * 16; i += 256) {
        int r = i >> 4;
        int c4 = (i & 15) * 4;
        float4 t = *(const float4*)&q[(s0 + r) * D + h * DH + c4];
        qs[r][c4 + 0] = t.x; qs[r][c4 + 1] = t.y; qs[r][c4 + 2] = t.z; qs[r][c4 + 3] = t.w;
    }

    int aty = tid >> 4, atx = tid & 15;
    int bty = tid >> 4, btx = tid & 15;
    float acc[4][4] = {};
    const float* gp = d_gpow + h * S;
    const float* Mh = d_M + (h * NC + cidx) * (DH * DH);
    __syncthreads();

    // ---- intra-chunk: 2 key tiles of 32 ----
    for (int t = 0; t < 2; t++) {
        int m0 = s0 + t * 32;
        for (int i = tid; i < 32 * 16; i += 256) {
            int r = i >> 4;
            int c4 = (i & 15) * 4;
            float4 kv = *(const float4*)&k[(m0 + r) * D + h * DH + c4];
            ks[r][c4 + 0] = kv.x; ks[r][c4 + 1] = kv.y; ks[r][c4 + 2] = kv.z; ks[r][c4 + 3] = kv.w;
            float4 vv = *(const float4*)&v[(m0 + r) * D + h * DH + c4];
            vs[r][c4 + 0] = vv.x; vs[r][c4 + 1] = vv.y; vs[r][c4 + 2] = vv.z; vs[r][c4 + 3] = vv.w;
        }
        __syncthreads();

        float sv[4][2] = {};
#pragma unroll 16
        for (int d = 0; d < 64; d++) {
            float qr0 = qs[aty * 4 + 0][d];
            float qr1 = qs[aty * 4 + 1][d];
            float qr2 = qs[aty * 4 + 2][d];
            float qr3 = qs[aty * 4 + 3][d];
            float kc0 = ks[atx * 2 + 0][d];
            float kc1 = ks[atx * 2 + 1][d];
            sv[0][0] += qr0 * kc0; sv[0][1] += qr0 * kc1;
            sv[1][0] += qr1 * kc0; sv[1][1] += qr1 * kc1;
            sv[2][0] += qr2 * kc0; sv[2][1] += qr2 * kc1;
            sv[3][0] += qr3 * kc0; sv[3][1] += qr3 * kc1;
        }
#pragma unroll
        for (int r = 0; r < 4; r++)
#pragma unroll
            for (int c = 0; c < 2; c++) {
                int qi = s0 + aty * 4 + r;
                int kj = m0 + atx * 2 + c;
                int dist = qi - kj;
                ss[aty * 4 + r][atx * 2 + c] = (dist >= 0) ? sv[r][c] * gp[dist] : 0.0f;
            }
        __syncthreads();

#pragma unroll 8
        for (int j = 0; j < 32; j++) {
            float vr0 = vs[j][btx * 4 + 0];
            float vr1 = vs[j][btx * 4 + 1];
            float vr2 = vs[j][btx * 4 + 2];
            float vr3 = vs[j][btx * 4 + 3];
            float s0r = ss[bty * 4 + 0][j];
            float s1r = ss[bty * 4 + 1][j];
            float s2r = ss[bty * 4 + 2][j];
            float s3r = ss[bty * 4 + 3][j];
            acc[0][0] += s0r * vr0; acc[0][1] += s0r * vr1; acc[0][2] += s0r * vr2; acc[0][3] += s0r * vr3;
            acc[1][0] += s1r * vr0; acc[1][1] += s1r * vr1; acc[1][2] += s1r * vr2; acc[1][3] += s1r * vr3;
            acc[2][0] += s2r * vr0; acc[2][1] += s2r * vr1; acc[2][2] += s2r * vr2; acc[2][3] += s2r * vr3;
            acc[3][0] += s3r * vr0; acc[3][1] += s3r * vr1; acc[3][2] += s3r * vr2; acc[3][3] += s3r * vr3;
        }
        __syncthreads();
    }

    // ---- cross-chunk: ret += (gamma^(i+1) q_i) @ M ----
    if (cidx > 0) {
        for (int t2 = 0; t2 < 2; t2++) {
            for (int i = tid; i < 32 * 16; i += 256) {
                int r = i >> 4;
                int c4 = (i & 15) * 4;
                float4 mv = *(const float4*)&Mh[(t2 * 32 + r) * DH + c4];
                vs[r][c4 + 0] = mv.x; vs[r][c4 + 1] = mv.y; vs[r][c4 + 2] = mv.z; vs[r][c4 + 3] = mv.w;
            }
            for (int i = tid; i < 64 * 32; i += 256) {
                int r = i >> 5;
                int j = i & 31;
                ss[r][j] = qs[r][t2 * 32 + j] * gp[r + 1];
            }
            __syncthreads();
#pragma unroll 8
            for (int j = 0; j < 32; j++) {
                float vr0 = vs[j][btx * 4 + 0];
                float vr1 = vs[j][btx * 4 + 1];
                float vr2 = vs[j][btx * 4 + 2];
                float vr3 = vs[j][btx * 4 + 3];
                float s0r = ss[bty * 4 + 0][j];
                float s1r = ss[bty * 4 + 1][j];
                float s2r = ss[bty * 4 + 2][j];
                float s3r = ss[bty * 4 + 3][j];
                acc[0][0] += s0r * vr0; acc[0][1] += s0r * vr1; acc[0][2] += s0r * vr2; acc[0][3] += s0r * vr3;
                acc[1][0] += s1r * vr0; acc[1][1] += s1r * vr1; acc[1][2] += s1r * vr2; acc[1][3] += s1r * vr3;
                acc[2][0] += s2r * vr0; acc[2][1] += s2r * vr1; acc[2][2] += s2r * vr2; acc[2][3] += s2r * vr3;
                acc[3][0] += s3r * vr0; acc[3][1] += s3r * vr1; acc[3][2] += s3r * vr2; acc[3][3] += s3r * vr3;
            }
            __syncthreads();
        }
    }

    // ---- groupnorm over DH, write ----
#pragma unroll
    for (int r = 0; r < 4; r++)
#pragma unroll
        for (int c = 0; c < 4; c++)
            qs[bty * 4 + r][btx * 4 + c] = acc[r][c];
    __syncthreads();

    if (tid < 64) {
        int i = tid;
        float mu = 0.0f;
#pragma unroll 16
        for (int d = 0; d < 64; d++) mu += qs[i][d];
        mu *= (1.0f / 64.0f);
        float var = 0.0f;
#pragma unroll 16
        for (int d = 0; d < 64; d++) {
            float dd = qs[i][d] - mu;
            var += dd * dd;
        }
        var *= (1.0f / 64.0f);
        float rs = rsqrtf(var + 1e-6f);
#pragma unroll 16
        for (int d = 0; d < 64; d++)
            ret[(s0 + i) * D + h * DH + d] = (qs[i][d] - mu) * rs;
    }
}

// ---------------- final: out[s] = sigmoid(x[s,:] . Wout + bout) ----------------
__global__ void final_kernel(const float* __restrict__ Wout, const float* __restrict__ bout,
                             float* __restrict__ out) {
    int row = blockIdx.x;
    int t = threadIdx.x;   // 64
    float s = 0.0f;
    for (int i = t; i < D; i += 64) s += d_x[row * D + i] * Wout[i];
    __shared__ float red[64];
    red[t] = s;
    __syncthreads();
    for (int o = 32; o > 0; o >>= 1) {
        if (t < o) red[t] += red[t + o];
        __syncthreads();
    }
    if (t == 0) out[row] = 1.0f / (1.0f + expf(-(red[0] + bout[0])));
}

// ---------------- host orchestration ----------------
extern "C" void kernel_launch(void* const* d_in, const int* in_sizes, int n_in,
                              void* d_out, int out_size) {
    const float* x_in  = (const float*)d_in[0];
    const float* pe    = (const float*)d_in[1];
    const float* Wq    = (const float*)d_in[2];
    const float* bq    = (const float*)d_in[3];
    const float* Wk    = (const float*)d_in[4];
    const float* bk    = (const float*)d_in[5];
    const float* Wv    = (const float*)d_in[6];
    const float* bv    = (const float*)d_in[7];
    const float* Wg    = (const float*)d_in[8];
    const float* bg    = (const float*)d_in[9];
    const float* Wo    = (const float*)d_in[10];
    const float* bo    = (const float*)d_in[11];
    const float* ln1w  = (const float*)d_in[12];
    const float* ln1b  = (const float*)d_in[13];
    const float* ln2w  = (const float*)d_in[14];
    const float* ln2b  = (const float*)d_in[15];
    const float* W1    = (const float*)d_in[16];
    const float* b1    = (const float*)d_in[17];
    const float* W2    = (const float*)d_in[18];
    const float* b2    = (const float*)d_in[19];
    const float* Wout  = (const float*)d_in[20];
    const float* bout  = (const float*)d_in[21];
    float* out = (float*)d_out;

    void *px_, *py_, *pq_, *pk_, *pv_, *pg_, *pret_, *pff_;
    cudaGetSymbolAddress(&px_,  d_x);
    cudaGetSymbolAddress(&py_,  d_y);
    cudaGetSymbolAddress(&pq_,  d_q);
    cudaGetSymbolAddress(&pk_,  d_k);
    cudaGetSymbolAddress(&pv_,  d_v);
    cudaGetSymbolAddress(&pg_,  d_g);
    cudaGetSymbolAddress(&pret_, d_ret);
    cudaGetSymbolAddress(&pff_, d_ff);
    float* px   = (float*)px_;
    float* py   = (float*)py_;
    float* pq   = (float*)pq_;
    float* pk   = (float*)pk_;
    float* pv   = (float*)pv_;
    float* pg   = (float*)pg_;
    float* pret = (float*)pret_;
    float* pff  = (float*)pff_;

    init_tables_kernel<<<(S * 32 + 255) / 256, 256>>>();
    add_pos_kernel<<<(S * D + 255) / 256, 256>>>(x_in, pe);

    dim3 grid_qkvg(D / 128, S / 128, 4);     // (4,16,4) = 256 blocks
    dim3 grid_ff1(FF / 128, S / 128);        // (16,16)  = 256 blocks
    dim3 grid_64(D / 128, S / 64);           // (4,32)   = 128 blocks
    dim3 grid_ret(NC, H);                    // (32,8)   = 256 blocks

    for (int l = 0; l < L; l++) {
        layernorm_kernel<<<S, 256>>>(px, ln1w + l * D, ln1b + l * D, py, 1e-5f);

        qkvg_gemm<<<grid_qkvg, 256>>>(py,
            Wq + l * D * D, Wk + l * D * D, Wv + l * D * D, Wg + l * D * D,
            bq + l * D, bk + l * D, bv + l * D, bg + l * D);

        chunk_kv_kernel<<<grid_ret, 256>>>(pk, pv);
        scan_kernel<<<(H * DH * DH + 255) / 256, 256>>>();
        retn_kernel<<<grid_ret, 256>>>(pq, pk, pv, pret);

        // x += (g*ret) @ Wo + bo   (A-side elementwise product fused)
        gemm64_res<D, true><<<grid_64, 256>>>(pg, pret, Wo + l * D * D, bo + l * D, px);

        layernorm_kernel<<<S, 256>>>(px, ln2w + l * D, ln2b + l * D, py, 1e-5f);
        ffn1_gemm<<<grid_ff1, 256>>>(py, W1 + l * D * FF, b1 + l * FF);
        gemm64_res<FF, false><<<grid_64, 256>>>(pff, pff, W2 + l * FF * D, b2 + l * D, px);
    }

    final_kernel<<<S, 64>>>(Wout, bout, out);
}

// round 13
// speedup vs baseline: 1.2459x; 1.2459x over previous
#include <cuda_runtime.h>
#include <cuda_bf16.h>
#include <mma.h>
#include <math.h>
#include <stdint.h>

using namespace nvcuda;
typedef __nv_bfloat16 bf16;

#define S 2048
#define D 512
#define H 8
#define DH 64
#define L 4
#define FF 2048
#define NC (S / 64)
#define DD (D * D)

// ---------------- scratch (static device globals; no allocation) ----------------
__device__ float d_x  [S * D];
__device__ float d_q  [S * D];
__device__ float d_k  [S * D];
__device__ float d_v  [S * D];
__device__ float d_g  [S * D];
__device__ float d_ret[S * D];
__device__ float d_sin[S * (DH / 2)];
__device__ float d_cos[S * (DH / 2)];
__device__ float d_gpow[H * S];
__device__ float d_U[H * NC * DH * DH];
__device__ float d_M[H * NC * DH * DH];

__device__ __align__(16) bf16 d_yh [S * D];
__device__ __align__(16) bf16 d_yl [S * D];
__device__ __align__(16) bf16 d_grh[S * D];
__device__ __align__(16) bf16 d_grl[S * D];
__device__ __align__(16) bf16 d_ffh[S * FF];
__device__ __align__(16) bf16 d_ffl[S * FF];

// split weights, NATIVE [K][N] layout (row-major B for wmma). slot l*5+t for {q,k,v,g,o}
__device__ __align__(16) bf16 d_W5h[20 * DD];
__device__ __align__(16) bf16 d_W5l[20 * DD];
__device__ __align__(16) bf16 d_W1h[4 * D * FF];   // [D][FF]
__device__ __align__(16) bf16 d_W1l[4 * D * FF];
__device__ __align__(16) bf16 d_W2h[4 * FF * D];   // [FF][D]
__device__ __align__(16) bf16 d_W2l[4 * FF * D];

// ---------------- helpers ----------------
__device__ __forceinline__ uint32_t smem_to_u32(const void* p) {
    uint32_t a;
    asm("{ .reg .u64 t; cvta.to.shared.u64 t, %1; cvt.u32.u64 %0, t; }" : "=r"(a) : "l"(p));
    return a;
}
__device__ __forceinline__ void cp16(uint32_t dst, const void* src) {
    asm volatile("cp.async.cg.shared.global [%0], [%1], 16;" :: "r"(dst), "l"(src));
}
#define CP_COMMIT() asm volatile("cp.async.commit_group;" ::: "memory")
#define CP_WAIT0()  asm volatile("cp.async.wait_group 0;" ::: "memory")

// ---------------- setup tables ----------------
__global__ void init_tables_kernel() {
    int idx = blockIdx.x * blockDim.x + threadIdx.x;
    if (idx < S * (DH / 2)) {
        int s = idx / (DH / 2);
        int j = idx % (DH / 2);
        double theta = pow(10000.0, -(double)(2 * j) / (double)DH);
        double ang = (double)s * theta;
        d_sin[idx] = (float)sin(ang);
        d_cos[idx] = (float)cos(ang);
    }
    if (idx < H * S) {
        int h = idx / S;
        int dd = idx % S;
        double lg0 = log(1.0 / 32.0);
        double lg1 = log(1.0 / 512.0);
        double gamma = 1.0 - exp(lg0 + (lg1 - lg0) * (double)h / 7.0);
        d_gpow[idx] = (float)exp((double)dd * log(gamma));
    }
}

__global__ void add_pos_kernel(const float* __restrict__ x, const float* __restrict__ pe) {
    int i = blockIdx.x * blockDim.x + threadIdx.x;
    if (i < S * D) d_x[i] = x[i] + pe[i % D];
}

// ---------------- weight split (elementwise, layout preserved) ----------------
__global__ void wsplit_kernel(const float* __restrict__ src,
                              bf16* __restrict__ dh, bf16* __restrict__ dl,
                              int n, int dmul, int dadd) {
    int z = blockIdx.z;
    int i = blockIdx.x * blockDim.x + threadIdx.x;
    if (i >= n) return;
    float v = src[(size_t)z * n + i];
    size_t o = (size_t)(z * dmul + dadd) * n + i;
    bf16 h = __float2bfloat16(v);
    dh[o] = h;
    dl[o] = __float2bfloat16(v - __bfloat162float(h));
}

// ---------------- layernorm -> bf16 hi/lo ----------------
__global__ void layernorm_split(const float* __restrict__ in,
                                const float* __restrict__ w, const float* __restrict__ b,
                                float eps) {
    int row = blockIdx.x;
    int t = threadIdx.x;
    const float* xr = in + row * D;
    __shared__ float red[256];
    float v0 = xr[t];
    float v1 = xr[t + 256];
    red[t] = v0 + v1;
    __syncthreads();
    for (int o = 128; o > 0; o >>= 1) { if (t < o) red[t] += red[t + o]; __syncthreads(); }
    float mu = red[0] * (1.0f / D);
    __syncthreads();
    float a0 = v0 - mu, a1 = v1 - mu;
    red[t] = a0 * a0 + a1 * a1;
    __syncthreads();
    for (int o = 128; o > 0; o >>= 1) { if (t < o) red[t] += red[t + o]; __syncthreads(); }
    float rstd = rsqrtf(red[0] * (1.0f / D) + eps);
    float o0 = a0 * rstd * w[t] + b[t];
    float o1 = a1 * rstd * w[t + 256] + b[t + 256];
    bf16 h0 = __float2bfloat16(o0);
    bf16 h1 = __float2bfloat16(o1);
    d_yh[row * D + t] = h0;
    d_yl[row * D + t] = __float2bfloat16(o0 - __bfloat162float(h0));
    d_yh[row * D + t + 256] = h1;
    d_yl[row * D + t + 256] = __float2bfloat16(o1 - __bfloat162float(h1));
}

// ---------------- g*ret split ----------------
__global__ void mul_split_kernel() {
    int i = blockIdx.x * blockDim.x + threadIdx.x;
    if (i >= S * D) return;
    float v = d_g[i] * d_ret[i];
    bf16 h = __float2bfloat16(v);
    d_grh[i] = h;
    d_grl[i] = __float2bfloat16(v - __bfloat162float(h));
}

// ================= wmma bf16 GEMM core (3-term compensation) =================
// BM=128, BN=128, BK=64, 512 threads, 16 warps as 4x4 (32x32 per warp).
// smem buffer: Ah[128][72] | Al[128][72] | Bh[64][136] | Bl[64][136], double-buffered.
#define ASTRIDE 72
#define BSTRIDE 136
#define OFF_AH 0
#define OFF_AL 18432
#define OFF_BH 36864
#define OFF_BL 54272
#define BUFBYTES 71680
#define SMEM_TOT (2 * BUFBYTES)   // 143360

template <int KDIM, int NDIM>
__device__ __forceinline__ void issue_chunk(const bf16* __restrict__ Ah,
                                            const bf16* __restrict__ Al,
                                            const bf16* __restrict__ Bh,
                                            const bf16* __restrict__ Bl,
                                            uint32_t bufbase, int row0, int col0,
                                            int kc, int tid) {
#pragma unroll
    for (int i = 0; i < 2; i++) {
        int e = tid + i * 512;
        int r = e >> 3, c8 = (e & 7) * 8;
        uint32_t doff = (uint32_t)(r * ASTRIDE + c8) * 2;
        cp16(bufbase + OFF_AH + doff, Ah + (size_t)(row0 + r) * KDIM + kc + c8);
        cp16(bufbase + OFF_AL + doff, Al + (size_t)(row0 + r) * KDIM + kc + c8);
    }
#pragma unroll
    for (int i = 0; i < 2; i++) {
        int e = tid + i * 512;
        int r = e >> 4, n8 = (e & 15) * 8;
        uint32_t doff = (uint32_t)(r * BSTRIDE + n8) * 2;
        cp16(bufbase + OFF_BH + doff, Bh + (size_t)(kc + r) * NDIM + col0 + n8);
        cp16(bufbase + OFF_BL + doff, Bl + (size_t)(kc + r) * NDIM + col0 + n8);
    }
    CP_COMMIT();
}

template <int KDIM, int NDIM>
__device__ __forceinline__ void wmma_core(const bf16* __restrict__ Ah,
                                          const bf16* __restrict__ Al,
                                          const bf16* __restrict__ Bh,
                                          const bf16* __restrict__ Bl,
                                          char* smem, int row0, int col0) {
    const int tid = threadIdx.x;
    const int warp = tid >> 5;
    const int wr = (warp >> 2) * 32;
    const int wc = (warp & 3) * 32;
    const uint32_t sb = smem_to_u32(smem);

    wmma::fragment<wmma::accumulator, 16, 16, 16, float> acc[2][2];
#pragma unroll
    for (int m = 0; m < 2; m++)
#pragma unroll
        for (int n = 0; n < 2; n++) wmma::fill_fragment(acc[m][n], 0.0f);

    issue_chunk<KDIM, NDIM>(Ah, Al, Bh, Bl, sb, row0, col0, 0, tid);
    CP_WAIT0();
    __syncthreads();

    int buf = 0;
    for (int kc = 0; kc < KDIM; kc += 64) {
        bool more = (kc + 64 < KDIM);
        if (more)
            issue_chunk<KDIM, NDIM>(Ah, Al, Bh, Bl, sb + (buf ^ 1) * BUFBYTES,
                                    row0, col0, kc + 64, tid);

        const bf16* ash = (const bf16*)(smem + buf * BUFBYTES + OFF_AH);
        const bf16* asl = (const bf16*)(smem + buf * BUFBYTES + OFF_AL);
        const bf16* bsh = (const bf16*)(smem + buf * BUFBYTES + OFF_BH);
        const bf16* bsl = (const bf16*)(smem + buf * BUFBYTES + OFF_BL);

#pragma unroll
        for (int ks = 0; ks < 4; ks++) {
            wmma::fragment<wmma::matrix_a, 16, 16, 16, bf16, wmma::row_major> fa_h[2], fa_l[2];
#pragma unroll
            for (int m = 0; m < 2; m++) {
                wmma::load_matrix_sync(fa_h[m], ash + (wr + m * 16) * ASTRIDE + ks * 16, ASTRIDE);
                wmma::load_matrix_sync(fa_l[m], asl + (wr + m * 16) * ASTRIDE + ks * 16, ASTRIDE);
            }
#pragma unroll
            for (int n = 0; n < 2; n++) {
                wmma::fragment<wmma::matrix_b, 16, 16, 16, bf16, wmma::row_major> fb_h, fb_l;
                wmma::load_matrix_sync(fb_h, bsh + (ks * 16) * BSTRIDE + wc + n * 16, BSTRIDE);
                wmma::load_matrix_sync(fb_l, bsl + (ks * 16) * BSTRIDE + wc + n * 16, BSTRIDE);
#pragma unroll
                for (int m = 0; m < 2; m++) {
                    wmma::mma_sync(acc[m][n], fa_h[m], fb_h, acc[m][n]);
                    wmma::mma_sync(acc[m][n], fa_h[m], fb_l, acc[m][n]);
                    wmma::mma_sync(acc[m][n], fa_l[m], fb_h, acc[m][n]);
                }
            }
        }
        if (more) {
            CP_WAIT0();
            __syncthreads();
            buf ^= 1;
        }
    }

    // stage result tile into smem as f32 [128][132]
    __syncthreads();
    float* stage = (float*)smem;
#pragma unroll
    for (int m = 0; m < 2; m++)
#pragma unroll
        for (int n = 0; n < 2; n++)
            wmma::store_matrix_sync(stage + (wr + m * 16) * 132 + wc + n * 16,
                                    acc[m][n], 132, wmma::mem_row_major);
    __syncthreads();
}

// ---- qkvg: z=0:q(rope*0.125) 1:k(rope) 2:v 3:g(silu); f32 outputs ----
__global__ void __launch_bounds__(512) qkvg_wmma(
    const bf16* __restrict__ Ah, const bf16* __restrict__ Al,
    const bf16* __restrict__ W5h, const bf16* __restrict__ W5l,
    const float* __restrict__ bq, const float* __restrict__ bk,
    const float* __restrict__ bv, const float* __restrict__ bg) {
    extern __shared__ char smem[];
    int tid = threadIdx.x;
    int z = blockIdx.z;
    int row0 = blockIdx.y * 128, col0 = blockIdx.x * 128;
    const bf16* Bh = W5h + (size_t)z * DD;
    const bf16* Bl = W5l + (size_t)z * DD;
    const float* bias = (z == 0) ? bq : (z == 1) ? bk : (z == 2) ? bv : bg;
    float* out = (z == 0) ? d_q : (z == 1) ? d_k : (z == 2) ? d_v : d_g;

    wmma_core<D, D>(Ah, Al, Bh, Bl, smem, row0, col0);

    float (*st)[132] = (float (*)[132])smem;
    for (int i = tid; i < 4096; i += 512) {
        int r = i >> 5, c4 = (i & 31) * 4;
        int row = row0 + r, col = col0 + c4;
        float v0 = st[r][c4 + 0] + bias[col + 0];
        float v1 = st[r][c4 + 1] + bias[col + 1];
        float v2 = st[r][c4 + 2] + bias[col + 2];
        float v3 = st[r][c4 + 3] + bias[col + 3];
        float4 o;
        if (z <= 1) {
            int j = (col & 63) >> 1;
            float c0 = d_cos[row * 32 + j],     s0 = d_sin[row * 32 + j];
            float c1 = d_cos[row * 32 + j + 1], s1 = d_sin[row * 32 + j + 1];
            float sc = (z == 0) ? 0.125f : 1.0f;
            o.x = (v0 * c0 - v1 * s0) * sc;
            o.y = (v1 * c0 + v0 * s0) * sc;
            o.z = (v2 * c1 - v3 * s1) * sc;
            o.w = (v3 * c1 + v2 * s1) * sc;
        } else if (z == 2) {
            o = make_float4(v0, v1, v2, v3);
        } else {
            o.x = v0 / (1.0f + expf(-v0));
            o.y = v1 / (1.0f + expf(-v1));
            o.z = v2 / (1.0f + expf(-v2));
            o.w = v3 / (1.0f + expf(-v3));
        }
        *(float4*)&out[(size_t)row * D + col] = o;
    }
}

// ---- ffn1: SiLU -> bf16 hi/lo ----
__global__ void __launch_bounds__(512) ff1_wmma(
    const bf16* __restrict__ Ah, const bf16* __restrict__ Al,
    const bf16* __restrict__ Bh, const bf16* __restrict__ Bl,
    const float* __restrict__ bias) {
    extern __shared__ char smem[];
    int tid = threadIdx.x;
    int row0 = blockIdx.y * 128, col0 = blockIdx.x * 128;

    wmma_core<D, FF>(Ah, Al, Bh, Bl, smem, row0, col0);

    float (*st)[132] = (float (*)[132])smem;
    for (int i = tid; i < 4096; i += 512) {
        int r = i >> 5, c4 = (i & 31) * 4;
        int row = row0 + r, col = col0 + c4;
        size_t o = (size_t)row * FF + col;
#pragma unroll
        for (int j2 = 0; j2 < 4; j2++) {
            float t = st[r][c4 + j2] + bias[col + j2];
            float v = t / (1.0f + expf(-t));
            bf16 h = __float2bfloat16(v);
            d_ffh[o + j2] = h;
            d_ffl[o + j2] = __float2bfloat16(v - __bfloat162float(h));
        }
    }
}

// ---- residual GEMM: d_x += A@W + bias ----
template <int KDIM>
__global__ void __launch_bounds__(512) res_wmma(
    const bf16* __restrict__ Ah, const bf16* __restrict__ Al,
    const bf16* __restrict__ Bh, const bf16* __restrict__ Bl,
    const float* __restrict__ bias) {
    extern __shared__ char smem[];
    int tid = threadIdx.x;
    int row0 = blockIdx.y * 128, col0 = blockIdx.x * 128;

    wmma_core<KDIM, D>(Ah, Al, Bh, Bl, smem, row0, col0);

    float (*st)[132] = (float (*)[132])smem;
    for (int i = tid; i < 4096; i += 512) {
        int r = i >> 5, c4 = (i & 31) * 4;
        int row = row0 + r, col = col0 + c4;
        float4 oldv = *(float4*)&d_x[(size_t)row * D + col];
        float4 o;
        o.x = st[r][c4 + 0] + bias[col + 0] + oldv.x;
        o.y = st[r][c4 + 1] + bias[col + 1] + oldv.y;
        o.z = st[r][c4 + 2] + bias[col + 2] + oldv.z;
        o.w = st[r][c4 + 3] + bias[col + 3] + oldv.w;
        *(float4*)&d_x[(size_t)row * D + col] = o;
    }
}

// ================= chunked retention (unchanged, known-good) =================
__global__ void chunk_kv_kernel(const float* __restrict__ k, const float* __restrict__ v) {
    __shared__ float ks[64][68];
    __shared__ float vs[64][68];
    int c = blockIdx.x, h = blockIdx.y;
    int s0 = c * 64;
    int tid = threadIdx.x;
    const float* gp = d_gpow + h * S;

    for (int i = tid; i < 64 * 16; i += 256) {
        int r = i >> 4;
        int c4 = (i & 15) * 4;
        float g = gp[63 - r];
        float4 kv = *(const float4*)&k[(s0 + r) * D + h * DH + c4];
        ks[r][c4 + 0] = kv.x * g; ks[r][c4 + 1] = kv.y * g;
        ks[r][c4 + 2] = kv.z * g; ks[r][c4 + 3] = kv.w * g;
        float4 vv = *(const float4*)&v[(s0 + r) * D + h * DH + c4];
        vs[r][c4 + 0] = vv.x; vs[r][c4 + 1] = vv.y;
        vs[r][c4 + 2] = vv.z; vs[r][c4 + 3] = vv.w;
    }
    __syncthreads();

    int tx = tid & 15, ty = tid >> 4;
    float acc[4][4] = {};
#pragma unroll 8
    for (int p = 0; p < 64; p++) {
        float4 a = *(const float4*)&ks[p][ty * 4];
        float4 b = *(const float4*)&vs[p][tx * 4];
        acc[0][0] += a.x * b.x; acc[0][1] += a.x * b.y; acc[0][2] += a.x * b.z; acc[0][3] += a.x * b.w;
        acc[1][0] += a.y * b.x; acc[1][1] += a.y * b.y; acc[1][2] += a.y * b.z; acc[1][3] += a.y * b.w;
        acc[2][0] += a.z * b.x; acc[2][1] += a.z * b.y; acc[2][2] += a.z * b.z; acc[2][3] += a.z * b.w;
        acc[3][0] += a.w * b.x; acc[3][1] += a.w * b.y; acc[3][2] += a.w * b.z; acc[3][3] += a.w * b.w;
    }
    float* U = d_U + (h * NC + c) * (DH * DH);
#pragma unroll
    for (int r = 0; r < 4; r++)
        *(float4*)&U[(ty * 4 + r) * DH + tx * 4] = make_float4(acc[r][0], acc[r][1], acc[r][2], acc[r][3]);
}

__global__ void scan_kernel() {
    int e = blockIdx.x * blockDim.x + threadIdx.x;
    if (e >= H * DH * DH) return;
    int h = e >> 12;
    int idx = e & 4095;
    float gc = d_gpow[h * S + 64];
    float m = 0.0f;
    for (int c = 0; c < NC; c++) {
        d_M[(h * NC + c) * 4096 + idx] = m;
        m = gc * m + d_U[(h * NC + c) * 4096 + idx];
    }
}

__global__ void retn_kernel(const float* __restrict__ q, const float* __restrict__ k,
                            const float* __restrict__ v, float* __restrict__ ret) {
    __shared__ float qs[64][65];
    __shared__ float ks[32][65];
    __shared__ float vs[32][65];
    __shared__ float ss[64][33];

    int h = blockIdx.y;
    int cidx = blockIdx.x;
    int s0 = cidx * 64;
    int tid = threadIdx.x;

    for (int i = tid; i < 64 * 16; i += 256) {
        int r = i >> 4;
        int c4 = (i & 15) * 4;
        float4 t = *(const float4*)&q[(s0 + r) * D + h * DH + c4];
        qs[r][c4 + 0] = t.x; qs[r][c4 + 1] = t.y; qs[r][c4 + 2] = t.z; qs[r][c4 + 3] = t.w;
    }

    int aty = tid >> 4, atx = tid & 15;
    int bty = tid >> 4, btx = tid & 15;
    float acc[4][4] = {};
    const float* gp = d_gpow + h * S;
    const float* Mh = d_M + (h * NC + cidx) * (DH * DH);
    __syncthreads();

    for (int t = 0; t < 2; t++) {
        int m0 = s0 + t * 32;
        for (int i = tid; i < 32 * 16; i += 256) {
            int r = i >> 4;
            int c4 = (i & 15) * 4;
            float4 kv = *(const float4*)&k[(m0 + r) * D + h * DH + c4];
            ks[r][c4 + 0] = kv.x; ks[r][c4 + 1] = kv.y; ks[r][c4 + 2] = kv.z; ks[r][c4 + 3] = kv.w;
            float4 vv = *(const float4*)&v[(m0 + r) * D + h * DH + c4];
            vs[r][c4 + 0] = vv.x; vs[r][c4 + 1] = vv.y; vs[r][c4 + 2] = vv.z; vs[r][c4 + 3] = vv.w;
        }
        __syncthreads();

        float sv[4][2] = {};
#pragma unroll 16
        for (int d = 0; d < 64; d++) {
            float qr0 = qs[aty * 4 + 0][d];
            float qr1 = qs[aty * 4 + 1][d];
            float qr2 = qs[aty * 4 + 2][d];
            float qr3 = qs[aty * 4 + 3][d];
            float kc0 = ks[atx * 2 + 0][d];
            float kc1 = ks[atx * 2 + 1][d];
            sv[0][0] += qr0 * kc0; sv[0][1] += qr0 * kc1;
            sv[1][0] += qr1 * kc0; sv[1][1] += qr1 * kc1;
            sv[2][0] += qr2 * kc0; sv[2][1] += qr2 * kc1;
            sv[3][0] += qr3 * kc0; sv[3][1] += qr3 * kc1;
        }
#pragma unroll
        for (int r = 0; r < 4; r++)
#pragma unroll
            for (int c = 0; c < 2; c++) {
                int qi = s0 + aty * 4 + r;
                int kj = m0 + atx * 2 + c;
                int dist = qi - kj;
                ss[aty * 4 + r][atx * 2 + c] = (dist >= 0) ? sv[r][c] * gp[dist] : 0.0f;
            }
        __syncthreads();

#pragma unroll 8
        for (int j = 0; j < 32; j++) {
            float vr0 = vs[j][btx * 4 + 0];
            float vr1 = vs[j][btx * 4 + 1];
            float vr2 = vs[j][btx * 4 + 2];
            float vr3 = vs[j][btx * 4 + 3];
            float s0r = ss[bty * 4 + 0][j];
            float s1r = ss[bty * 4 + 1][j];
            float s2r = ss[bty * 4 + 2][j];
            float s3r = ss[bty * 4 + 3][j];
            acc[0][0] += s0r * vr0; acc[0][1] += s0r * vr1; acc[0][2] += s0r * vr2; acc[0][3] += s0r * vr3;
            acc[1][0] += s1r * vr0; acc[1][1] += s1r * vr1; acc[1][2] += s1r * vr2; acc[1][3] += s1r * vr3;
            acc[2][0] += s2r * vr0; acc[2][1] += s2r * vr1; acc[2][2] += s2r * vr2; acc[2][3] += s2r * vr3;
            acc[3][0] += s3r * vr0; acc[3][1] += s3r * vr1; acc[3][2] += s3r * vr2; acc[3][3] += s3r * vr3;
        }
        __syncthreads();
    }

    if (cidx > 0) {
        for (int t2 = 0; t2 < 2; t2++) {
            for (int i = tid; i < 32 * 16; i += 256) {
                int r = i >> 4;
                int c4 = (i & 15) * 4;
                float4 mv = *(const float4*)&Mh[(t2 * 32 + r) * DH + c4];
                vs[r][c4 + 0] = mv.x; vs[r][c4 + 1] = mv.y; vs[r][c4 + 2] = mv.z; vs[r][c4 + 3] = mv.w;
            }
            for (int i = tid; i < 64 * 32; i += 256) {
                int r = i >> 5;
                int j = i & 31;
                ss[r][j] = qs[r][t2 * 32 + j] * gp[r + 1];
            }
            __syncthreads();
#pragma unroll 8
            for (int j = 0; j < 32; j++) {
                float vr0 = vs[j][btx * 4 + 0];
                float vr1 = vs[j][btx * 4 + 1];
                float vr2 = vs[j][btx * 4 + 2];
                float vr3 = vs[j][btx * 4 + 3];
                float s0r = ss[bty * 4 + 0][j];
                float s1r = ss[bty * 4 + 1][j];
                float s2r = ss[bty * 4 + 2][j];
                float s3r = ss[bty * 4 + 3][j];
                acc[0][0] += s0r * vr0; acc[0][1] += s0r * vr1; acc[0][2] += s0r * vr2; acc[0][3] += s0r * vr3;
                acc[1][0] += s1r * vr0; acc[1][1] += s1r * vr1; acc[1][2] += s1r * vr2; acc[1][3] += s1r * vr3;
                acc[2][0] += s2r * vr0; acc[2][1] += s2r * vr1; acc[2][2] += s2r * vr2; acc[2][3] += s2r * vr3;
                acc[3][0] += s3r * vr0; acc[3][1] += s3r * vr1; acc[3][2] += s3r * vr2; acc[3][3] += s3r * vr3;
            }
            __syncthreads();
        }
    }

#pragma unroll
    for (int r = 0; r < 4; r++)
#pragma unroll
        for (int c = 0; c < 4; c++)
            qs[bty * 4 + r][btx * 4 + c] = acc[r][c];
    __syncthreads();

    if (tid < 64) {
        int i = tid;
        float mu = 0.0f;
#pragma unroll 16
        for (int d = 0; d < 64; d++) mu += qs[i][d];
        mu *= (1.0f / 64.0f);
        float var = 0.0f;
#pragma unroll 16
        for (int d = 0; d < 64; d++) {
            float dd = qs[i][d] - mu;
            var += dd * dd;
        }
        var *= (1.0f / 64.0f);
        float rs = rsqrtf(var + 1e-6f);
#pragma unroll 16
        for (int d = 0; d < 64; d++)
            ret[(s0 + i) * D + h * DH + d] = (qs[i][d] - mu) * rs;
    }
}

// ---------------- final ----------------
__global__ void final_kernel(const float* __restrict__ Wout, const float* __restrict__ bout,
                             float* __restrict__ out) {
    int row = blockIdx.x;
    int t = threadIdx.x;
    float s = 0.0f;
    for (int i = t; i < D; i += 64) s += d_x[row * D + i] * Wout[i];
    __shared__ float red[64];
    red[t] = s;
    __syncthreads();
    for (int o = 32; o > 0; o >>= 1) {
        if (t < o) red[t] += red[t + o];
        __syncthreads();
    }
    if (t == 0) out[row] = 1.0f / (1.0f + expf(-(red[0] + bout[0])));
}

// ---------------- host orchestration ----------------
extern "C" void kernel_launch(void* const* d_in, const int* in_sizes, int n_in,
                              void* d_out, int out_size) {
    const float* x_in  = (const float*)d_in[0];
    const float* pe    = (const float*)d_in[1];
    const float* Wq    = (const float*)d_in[2];
    const float* bq    = (const float*)d_in[3];
    const float* Wk    = (const float*)d_in[4];
    const float* bk    = (const float*)d_in[5];
    const float* Wv    = (const float*)d_in[6];
    const float* bv    = (const float*)d_in[7];
    const float* Wg    = (const float*)d_in[8];
    const float* bg    = (const float*)d_in[9];
    const float* Wo    = (const float*)d_in[10];
    const float* bo    = (const float*)d_in[11];
    const float* ln1w  = (const float*)d_in[12];
    const float* ln1b  = (const float*)d_in[13];
    const float* ln2w  = (const float*)d_in[14];
    const float* ln2b  = (const float*)d_in[15];
    const float* W1    = (const float*)d_in[16];
    const float* b1    = (const float*)d_in[17];
    const float* W2    = (const float*)d_in[18];
    const float* b2    = (const float*)d_in[19];
    const float* Wout  = (const float*)d_in[20];
    const float* bout  = (const float*)d_in[21];
    float* out = (float*)d_out;

    void* p;
    cudaGetSymbolAddress(&p, d_x);    float* px = (float*)p;
    cudaGetSymbolAddress(&p, d_q);    float* pq = (float*)p;
    cudaGetSymbolAddress(&p, d_k);    float* pk = (float*)p;
    cudaGetSymbolAddress(&p, d_v);    float* pv = (float*)p;
    cudaGetSymbolAddress(&p, d_ret);  float* pret = (float*)p;
    cudaGetSymbolAddress(&p, d_yh);   bf16* pyh = (bf16*)p;
    cudaGetSymbolAddress(&p, d_yl);   bf16* pyl = (bf16*)p;
    cudaGetSymbolAddress(&p, d_grh);  bf16* pgrh = (bf16*)p;
    cudaGetSymbolAddress(&p, d_grl);  bf16* pgrl = (bf16*)p;
    cudaGetSymbolAddress(&p, d_ffh);  bf16* pffh = (bf16*)p;
    cudaGetSymbolAddress(&p, d_ffl);  bf16* pffl = (bf16*)p;
    cudaGetSymbolAddress(&p, d_W5h);  bf16* pW5h = (bf16*)p;
    cudaGetSymbolAddress(&p, d_W5l);  bf16* pW5l = (bf16*)p;
    cudaGetSymbolAddress(&p, d_W1h);  bf16* pW1h = (bf16*)p;
    cudaGetSymbolAddress(&p, d_W1l);  bf16* pW1l = (bf16*)p;
    cudaGetSymbolAddress(&p, d_W2h);  bf16* pW2h = (bf16*)p;
    cudaGetSymbolAddress(&p, d_W2l);  bf16* pW2l = (bf16*)p;

    cudaFuncSetAttribute(qkvg_wmma,    cudaFuncAttributeMaxDynamicSharedMemorySize, SMEM_TOT);
    cudaFuncSetAttribute(ff1_wmma,     cudaFuncAttributeMaxDynamicSharedMemorySize, SMEM_TOT);
    cudaFuncSetAttribute(res_wmma<D>,  cudaFuncAttributeMaxDynamicSharedMemorySize, SMEM_TOT);
    cudaFuncSetAttribute(res_wmma<FF>, cudaFuncAttributeMaxDynamicSharedMemorySize, SMEM_TOT);

    init_tables_kernel<<<(S * 32 + 255) / 256, 256>>>();
    add_pos_kernel<<<(S * D + 255) / 256, 256>>>(x_in, pe);

    // weight splits (layout preserved)
    {
        dim3 g5(DD / 256, 1, L);
        wsplit_kernel<<<g5, 256>>>(Wq, pW5h, pW5l, DD, 5, 0);
        wsplit_kernel<<<g5, 256>>>(Wk, pW5h, pW5l, DD, 5, 1);
        wsplit_kernel<<<g5, 256>>>(Wv, pW5h, pW5l, DD, 5, 2);
        wsplit_kernel<<<g5, 256>>>(Wg, pW5h, pW5l, DD, 5, 3);
        wsplit_kernel<<<g5, 256>>>(Wo, pW5h, pW5l, DD, 5, 4);
        dim3 g1((D * FF) / 256, 1, L);
        wsplit_kernel<<<g1, 256>>>(W1, pW1h, pW1l, D * FF, 1, 0);
        wsplit_kernel<<<g1, 256>>>(W2, pW2h, pW2l, FF * D, 1, 0);
    }

    dim3 grid_qkvg(D / 128, S / 128, 4);
    dim3 grid_ff1(FF / 128, S / 128);
    dim3 grid_res(D / 128, S / 128);
    dim3 grid_ret(NC, H);

    for (int l = 0; l < L; l++) {
        layernorm_split<<<S, 256>>>(px, ln1w + l * D, ln1b + l * D, 1e-5f);

        qkvg_wmma<<<grid_qkvg, 512, SMEM_TOT>>>(pyh, pyl,
            pW5h + (size_t)l * 5 * DD, pW5l + (size_t)l * 5 * DD,
            bq + l * D, bk + l * D, bv + l * D, bg + l * D);

        chunk_kv_kernel<<<grid_ret, 256>>>(pk, pv);
        scan_kernel<<<(H * DH * DH + 255) / 256, 256>>>();
        retn_kernel<<<grid_ret, 256>>>(pq, pk, pv, pret);

        mul_split_kernel<<<(S * D + 255) / 256, 256>>>();
        res_wmma<D><<<grid_res, 512, SMEM_TOT>>>(pgrh, pgrl,
            pW5h + ((size_t)l * 5 + 4) * DD, pW5l + ((size_t)l * 5 + 4) * DD, bo + l * D);

        layernorm_split<<<S, 256>>>(px, ln2w + l * D, ln2b + l * D, 1e-5f);
        ff1_wmma<<<grid_ff1, 512, SMEM_TOT>>>(pyh, pyl,
            pW1h + (size_t)l * D * FF, pW1l + (size_t)l * D * FF, b1 + l * FF);
        res_wmma<FF><<<grid_res, 512, SMEM_TOT>>>(pffh, pffl,
            pW2h + (size_t)l * FF * D, pW2l + (size_t)l * FF * D, b2 + l * D);
    }

    final_kernel<<<S, 64>>>(Wout, bout, out);
}

// round 14
// speedup vs baseline: 1.3951x; 1.1198x over previous
#include <cuda_runtime.h>
#include <cuda_bf16.h>
#include <mma.h>
#include <math.h>
#include <stdint.h>

using namespace nvcuda;
typedef __nv_bfloat16 bf16;

#define S 2048
#define D 512
#define H 8
#define DH 64
#define L 4
#define FF 2048
#define NC (S / 64)
#define DD (D * D)

// ---------------- scratch (static device globals; no allocation) ----------------
__device__ float d_x  [S * D];
__device__ float d_q  [S * D];
__device__ float d_k  [S * D];
__device__ float d_v  [S * D];
__device__ float d_g  [S * D];
__device__ float d_ret[S * D];
__device__ float d_sin[S * (DH / 2)];
__device__ float d_cos[S * (DH / 2)];
__device__ float d_gpow[H * S];
__device__ float d_U[H * NC * DH * DH];
__device__ float d_M[H * NC * DH * DH];

__device__ __align__(16) bf16 d_yh [S * D];
__device__ __align__(16) bf16 d_yl [S * D];
__device__ __align__(16) bf16 d_grh[S * D];
__device__ __align__(16) bf16 d_grl[S * D];
__device__ __align__(16) bf16 d_ffh[S * FF];
__device__ __align__(16) bf16 d_ffl[S * FF];

// split weights, NATIVE [K][N] layout. slot l*5+t for {q,k,v,g,o}
__device__ __align__(16) bf16 d_W5h[20 * DD];
__device__ __align__(16) bf16 d_W5l[20 * DD];
__device__ __align__(16) bf16 d_W1h[4 * D * FF];   // [D][FF]
__device__ __align__(16) bf16 d_W1l[4 * D * FF];
__device__ __align__(16) bf16 d_W2h[4 * FF * D];   // [FF][D]
__device__ __align__(16) bf16 d_W2l[4 * FF * D];

// ---------------- helpers ----------------
__device__ __forceinline__ uint32_t smem_to_u32(const void* p) {
    uint32_t a;
    asm("{ .reg .u64 t; cvta.to.shared.u64 t, %1; cvt.u32.u64 %0, t; }" : "=r"(a) : "l"(p));
    return a;
}
__device__ __forceinline__ void cp16(uint32_t dst, const void* src) {
    asm volatile("cp.async.cg.shared.global [%0], [%1], 16;" :: "r"(dst), "l"(src));
}
#define CP_COMMIT() asm volatile("cp.async.commit_group;" ::: "memory")
#define CP_WAIT0()  asm volatile("cp.async.wait_group 0;" ::: "memory")

// ---------------- setup tables ----------------
__global__ void init_tables_kernel() {
    int idx = blockIdx.x * blockDim.x + threadIdx.x;
    if (idx < S * (DH / 2)) {
        int s = idx / (DH / 2);
        int j = idx % (DH / 2);
        double theta = pow(10000.0, -(double)(2 * j) / (double)DH);
        double ang = (double)s * theta;
        d_sin[idx] = (float)sin(ang);
        d_cos[idx] = (float)cos(ang);
    }
    if (idx < H * S) {
        int h = idx / S;
        int dd = idx % S;
        double lg0 = log(1.0 / 32.0);
        double lg1 = log(1.0 / 512.0);
        double gamma = 1.0 - exp(lg0 + (lg1 - lg0) * (double)h / 7.0);
        d_gpow[idx] = (float)exp((double)dd * log(gamma));
    }
}

__global__ void add_pos_kernel(const float* __restrict__ x, const float* __restrict__ pe) {
    int i = blockIdx.x * blockDim.x + threadIdx.x;
    if (i < S * D) d_x[i] = x[i] + pe[i % D];
}

// ---------------- weight split: all 5 D*D families in one launch ----------------
__global__ void wsplit5_kernel(const float* __restrict__ Wq, const float* __restrict__ Wk,
                               const float* __restrict__ Wv, const float* __restrict__ Wg,
                               const float* __restrict__ Wo,
                               bf16* __restrict__ dh, bf16* __restrict__ dl) {
    int z = blockIdx.z;               // 0..19 = l*5+t
    int l = z / 5, t = z % 5;
    const float* src = (t == 0) ? Wq : (t == 1) ? Wk : (t == 2) ? Wv : (t == 3) ? Wg : Wo;
    int i = blockIdx.x * blockDim.x + threadIdx.x;
    float v = src[(size_t)l * DD + i];
    size_t o = (size_t)z * DD + i;
    bf16 h = __float2bfloat16(v);
    dh[o] = h;
    dl[o] = __float2bfloat16(v - __bfloat162float(h));
}

__global__ void wsplit_kernel(const float* __restrict__ src,
                              bf16* __restrict__ dh, bf16* __restrict__ dl, int n) {
    int z = blockIdx.z;
    int i = blockIdx.x * blockDim.x + threadIdx.x;
    if (i >= n) return;
    float v = src[(size_t)z * n + i];
    size_t o = (size_t)z * n + i;
    bf16 h = __float2bfloat16(v);
    dh[o] = h;
    dl[o] = __float2bfloat16(v - __bfloat162float(h));
}

// ---------------- layernorm -> bf16 hi/lo ----------------
__global__ void layernorm_split(const float* __restrict__ in,
                                const float* __restrict__ w, const float* __restrict__ b,
                                float eps) {
    int row = blockIdx.x;
    int t = threadIdx.x;
    const float* xr = in + row * D;
    __shared__ float red[256];
    float v0 = xr[t];
    float v1 = xr[t + 256];
    red[t] = v0 + v1;
    __syncthreads();
    for (int o = 128; o > 0; o >>= 1) { if (t < o) red[t] += red[t + o]; __syncthreads(); }
    float mu = red[0] * (1.0f / D);
    __syncthreads();
    float a0 = v0 - mu, a1 = v1 - mu;
    red[t] = a0 * a0 + a1 * a1;
    __syncthreads();
    for (int o = 128; o > 0; o >>= 1) { if (t < o) red[t] += red[t + o]; __syncthreads(); }
    float rstd = rsqrtf(red[0] * (1.0f / D) + eps);
    float o0 = a0 * rstd * w[t] + b[t];
    float o1 = a1 * rstd * w[t + 256] + b[t + 256];
    bf16 h0 = __float2bfloat16(o0);
    bf16 h1 = __float2bfloat16(o1);
    d_yh[row * D + t] = h0;
    d_yl[row * D + t] = __float2bfloat16(o0 - __bfloat162float(h0));
    d_yh[row * D + t + 256] = h1;
    d_yl[row * D + t + 256] = __float2bfloat16(o1 - __bfloat162float(h1));
}

// ---------------- g*ret split ----------------
__global__ void mul_split_kernel() {
    int i = blockIdx.x * blockDim.x + threadIdx.x;
    if (i >= S * D) return;
    float v = d_g[i] * d_ret[i];
    bf16 h = __float2bfloat16(v);
    d_grh[i] = h;
    d_grl[i] = __float2bfloat16(v - __bfloat162float(h));
}

// ================= wmma bf16 GEMM core (3-term compensation) =================
// BM in {128, 64}, BN=128, BK=64, 512 threads, 16 warps as 4x4.
// Warp tile: (BM/4) x 32. MMA order term-major for pipeline depth.
#define ASTRIDE 72
#define BSTRIDE 136

template <int BM> struct CoreCfg {
    static constexpr int A_BYTES = BM * ASTRIDE * 2;
    static constexpr int B_BYTES = 64 * BSTRIDE * 2;       // 17408
    static constexpr int OFF_AL2 = A_BYTES;
    static constexpr int OFF_BH2 = 2 * A_BYTES;
    static constexpr int OFF_BL2 = 2 * A_BYTES + B_BYTES;
    static constexpr int BUF = 2 * A_BYTES + 2 * B_BYTES;
    static constexpr int MF = BM / 64;                      // m-fragments per warp
};

template <int KDIM, int NDIM, int BM>
__device__ __forceinline__ void issue_chunk(const bf16* __restrict__ Ah,
                                            const bf16* __restrict__ Al,
                                            const bf16* __restrict__ Bh,
                                            const bf16* __restrict__ Bl,
                                            uint32_t bufbase, int row0, int col0,
                                            int kc, int tid) {
    using C = CoreCfg<BM>;
#pragma unroll
    for (int i = 0; i < BM / 64; i++) {
        int e = tid + i * 512;
        int r = e >> 3, c8 = (e & 7) * 8;
        uint32_t doff = (uint32_t)(r * ASTRIDE + c8) * 2;
        cp16(bufbase + doff, Ah + (size_t)(row0 + r) * KDIM + kc + c8);
        cp16(bufbase + C::OFF_AL2 + doff, Al + (size_t)(row0 + r) * KDIM + kc + c8);
    }
#pragma unroll
    for (int i = 0; i < 2; i++) {
        int e = tid + i * 512;
        int r = e >> 4, n8 = (e & 15) * 8;
        uint32_t doff = (uint32_t)(r * BSTRIDE + n8) * 2;
        cp16(bufbase + C::OFF_BH2 + doff, Bh + (size_t)(kc + r) * NDIM + col0 + n8);
        cp16(bufbase + C::OFF_BL2 + doff, Bl + (size_t)(kc + r) * NDIM + col0 + n8);
    }
    CP_COMMIT();
}

template <int KDIM, int NDIM, int BM>
__device__ __forceinline__ void wmma_core(const bf16* __restrict__ Ah,
                                          const bf16* __restrict__ Al,
                                          const bf16* __restrict__ Bh,
                                          const bf16* __restrict__ Bl,
                                          char* smem, int row0, int col0) {
    using C = CoreCfg<BM>;
    constexpr int MF = C::MF;
    const int tid = threadIdx.x;
    const int warp = tid >> 5;
    const int wr = (warp >> 2) * (16 * MF);
    const int wc = (warp & 3) * 32;
    const uint32_t sb = smem_to_u32(smem);

    wmma::fragment<wmma::accumulator, 16, 16, 16, float> acc[MF][2];
#pragma unroll
    for (int m = 0; m < MF; m++)
#pragma unroll
        for (int n = 0; n < 2; n++) wmma::fill_fragment(acc[m][n], 0.0f);

    issue_chunk<KDIM, NDIM, BM>(Ah, Al, Bh, Bl, sb, row0, col0, 0, tid);
    CP_WAIT0();
    __syncthreads();

    int buf = 0;
    for (int kc = 0; kc < KDIM; kc += 64) {
        bool more = (kc + 64 < KDIM);
        if (more)
            issue_chunk<KDIM, NDIM, BM>(Ah, Al, Bh, Bl, sb + (buf ^ 1) * C::BUF,
                                        row0, col0, kc + 64, tid);

        const bf16* ash = (const bf16*)(smem + buf * C::BUF);
        const bf16* asl = (const bf16*)(smem + buf * C::BUF + C::OFF_AL2);
        const bf16* bsh = (const bf16*)(smem + buf * C::BUF + C::OFF_BH2);
        const bf16* bsl = (const bf16*)(smem + buf * C::BUF + C::OFF_BL2);

#pragma unroll
        for (int ks = 0; ks < 4; ks++) {
            wmma::fragment<wmma::matrix_a, 16, 16, 16, bf16, wmma::row_major> fa_h[MF], fa_l[MF];
            wmma::fragment<wmma::matrix_b, 16, 16, 16, bf16, wmma::row_major> fb_h[2], fb_l[2];
#pragma unroll
            for (int m = 0; m < MF; m++) {
                wmma::load_matrix_sync(fa_h[m], ash + (wr + m * 16) * ASTRIDE + ks * 16, ASTRIDE);
                wmma::load_matrix_sync(fa_l[m], asl + (wr + m * 16) * ASTRIDE + ks * 16, ASTRIDE);
            }
#pragma unroll
            for (int n = 0; n < 2; n++) {
                wmma::load_matrix_sync(fb_h[n], bsh + (ks * 16) * BSTRIDE + wc + n * 16, BSTRIDE);
                wmma::load_matrix_sync(fb_l[n], bsl + (ks * 16) * BSTRIDE + wc + n * 16, BSTRIDE);
            }
            // term-major order: max independent-MMA distance between acc reuses
#pragma unroll
            for (int n = 0; n < 2; n++)
#pragma unroll
                for (int m = 0; m < MF; m++)
                    wmma::mma_sync(acc[m][n], fa_h[m], fb_h[n], acc[m][n]);
#pragma unroll
            for (int n = 0; n < 2; n++)
#pragma unroll
                for (int m = 0; m < MF; m++)
                    wmma::mma_sync(acc[m][n], fa_h[m], fb_l[n], acc[m][n]);
#pragma unroll
            for (int n = 0; n < 2; n++)
#pragma unroll
                for (int m = 0; m < MF; m++)
                    wmma::mma_sync(acc[m][n], fa_l[m], fb_h[n], acc[m][n]);
        }
        if (more) {
            CP_WAIT0();
            __syncthreads();
            buf ^= 1;
        }
    }

    // stage result into smem as f32 [BM][132]
    __syncthreads();
    float* stage = (float*)smem;
#pragma unroll
    for (int m = 0; m < MF; m++)
#pragma unroll
        for (int n = 0; n < 2; n++)
            wmma::store_matrix_sync(stage + (wr + m * 16) * 132 + wc + n * 16,
                                    acc[m][n], 132, wmma::mem_row_major);
    __syncthreads();
}

#define SMEM_128 (2 * CoreCfg<128>::BUF)   // 143360
#define SMEM_64  (2 * CoreCfg<64>::BUF)    // 106496

// ---- qkvg: z=0:q(rope*0.125) 1:k(rope) 2:v 3:g(silu); f32 outputs ----
__global__ void __launch_bounds__(512) qkvg_wmma(
    const bf16* __restrict__ Ah, const bf16* __restrict__ Al,
    const bf16* __restrict__ W5h, const bf16* __restrict__ W5l,
    const float* __restrict__ bq, const float* __restrict__ bk,
    const float* __restrict__ bv, const float* __restrict__ bg) {
    extern __shared__ char smem[];
    int tid = threadIdx.x;
    int z = blockIdx.z;
    int row0 = blockIdx.y * 128, col0 = blockIdx.x * 128;
    const bf16* Bh = W5h + (size_t)z * DD;
    const bf16* Bl = W5l + (size_t)z * DD;
    const float* bias = (z == 0) ? bq : (z == 1) ? bk : (z == 2) ? bv : bg;
    float* out = (z == 0) ? d_q : (z == 1) ? d_k : (z == 2) ? d_v : d_g;

    wmma_core<D, D, 128>(Ah, Al, Bh, Bl, smem, row0, col0);

    float (*st)[132] = (float (*)[132])smem;
    for (int i = tid; i < 4096; i += 512) {
        int r = i >> 5, c4 = (i & 31) * 4;
        int row = row0 + r, col = col0 + c4;
        float v0 = st[r][c4 + 0] + bias[col + 0];
        float v1 = st[r][c4 + 1] + bias[col + 1];
        float v2 = st[r][c4 + 2] + bias[col + 2];
        float v3 = st[r][c4 + 3] + bias[col + 3];
        float4 o;
        if (z <= 1) {
            int j = (col & 63) >> 1;
            float c0 = d_cos[row * 32 + j],     s0 = d_sin[row * 32 + j];
            float c1 = d_cos[row * 32 + j + 1], s1 = d_sin[row * 32 + j + 1];
            float sc = (z == 0) ? 0.125f : 1.0f;
            o.x = (v0 * c0 - v1 * s0) * sc;
            o.y = (v1 * c0 + v0 * s0) * sc;
            o.z = (v2 * c1 - v3 * s1) * sc;
            o.w = (v3 * c1 + v2 * s1) * sc;
        } else if (z == 2) {
            o = make_float4(v0, v1, v2, v3);
        } else {
            o.x = v0 / (1.0f + expf(-v0));
            o.y = v1 / (1.0f + expf(-v1));
            o.z = v2 / (1.0f + expf(-v2));
            o.w = v3 / (1.0f + expf(-v3));
        }
        *(float4*)&out[(size_t)row * D + col] = o;
    }
}

// ---- ffn1: SiLU -> bf16 hi/lo ----
__global__ void __launch_bounds__(512) ff1_wmma(
    const bf16* __restrict__ Ah, const bf16* __restrict__ Al,
    const bf16* __restrict__ Bh, const bf16* __restrict__ Bl,
    const float* __restrict__ bias) {
    extern __shared__ char smem[];
    int tid = threadIdx.x;
    int row0 = blockIdx.y * 128, col0 = blockIdx.x * 128;

    wmma_core<D, FF, 128>(Ah, Al, Bh, Bl, smem, row0, col0);

    float (*st)[132] = (float (*)[132])smem;
    for (int i = tid; i < 4096; i += 512) {
        int r = i >> 5, c4 = (i & 31) * 4;
        int row = row0 + r, col = col0 + c4;
        size_t o = (size_t)row * FF + col;
#pragma unroll
        for (int j2 = 0; j2 < 4; j2++) {
            float t = st[r][c4 + j2] + bias[col + j2];
            float v = t / (1.0f + expf(-t));
            bf16 h = __float2bfloat16(v);
            d_ffh[o + j2] = h;
            d_ffl[o + j2] = __float2bfloat16(v - __bfloat162float(h));
        }
    }
}

// ---- residual GEMM (BM=64): d_x += A@W + bias ----
template <int KDIM>
__global__ void __launch_bounds__(512) res_wmma(
    const bf16* __restrict__ Ah, const bf16* __restrict__ Al,
    const bf16* __restrict__ Bh, const bf16* __restrict__ Bl,
    const float* __restrict__ bias) {
    extern __shared__ char smem[];
    int tid = threadIdx.x;
    int row0 = blockIdx.y * 64, col0 = blockIdx.x * 128;

    wmma_core<KDIM, D, 64>(Ah, Al, Bh, Bl, smem, row0, col0);

    float (*st)[132] = (float (*)[132])smem;
    for (int i = tid; i < 2048; i += 512) {
        int r = i >> 5, c4 = (i & 31) * 4;
        int row = row0 + r, col = col0 + c4;
        float4 oldv = *(float4*)&d_x[(size_t)row * D + col];
        float4 o;
        o.x = st[r][c4 + 0] + bias[col + 0] + oldv.x;
        o.y = st[r][c4 + 1] + bias[col + 1] + oldv.y;
        o.z = st[r][c4 + 2] + bias[col + 2] + oldv.z;
        o.w = st[r][c4 + 3] + bias[col + 3] + oldv.w;
        *(float4*)&d_x[(size_t)row * D + col] = o;
    }
}

// ================= chunked retention (unchanged, known-good) =================
__global__ void chunk_kv_kernel(const float* __restrict__ k, const float* __restrict__ v) {
    __shared__ float ks[64][68];
    __shared__ float vs[64][68];
    int c = blockIdx.x, h = blockIdx.y;
    int s0 = c * 64;
    int tid = threadIdx.x;
    const float* gp = d_gpow + h * S;

    for (int i = tid; i < 64 * 16; i += 256) {
        int r = i >> 4;
        int c4 = (i & 15) * 4;
        float g = gp[63 - r];
        float4 kv = *(const float4*)&k[(s0 + r) * D + h * DH + c4];
        ks[r][c4 + 0] = kv.x * g; ks[r][c4 + 1] = kv.y * g;
        ks[r][c4 + 2] = kv.z * g; ks[r][c4 + 3] = kv.w * g;
        float4 vv = *(const float4*)&v[(s0 + r) * D + h * DH + c4];
        vs[r][c4 + 0] = vv.x; vs[r][c4 + 1] = vv.y;
        vs[r][c4 + 2] = vv.z; vs[r][c4 + 3] = vv.w;
    }
    __syncthreads();

    int tx = tid & 15, ty = tid >> 4;
    float acc[4][4] = {};
#pragma unroll 8
    for (int p = 0; p < 64; p++) {
        float4 a = *(const float4*)&ks[p][ty * 4];
        float4 b = *(const float4*)&vs[p][tx * 4];
        acc[0][0] += a.x * b.x; acc[0][1] += a.x * b.y; acc[0][2] += a.x * b.z; acc[0][3] += a.x * b.w;
        acc[1][0] += a.y * b.x; acc[1][1] += a.y * b.y; acc[1][2] += a.y * b.z; acc[1][3] += a.y * b.w;
        acc[2][0] += a.z * b.x; acc[2][1] += a.z * b.y; acc[2][2] += a.z * b.z; acc[2][3] += a.z * b.w;
        acc[3][0] += a.w * b.x; acc[3][1] += a.w * b.y; acc[3][2] += a.w * b.z; acc[3][3] += a.w * b.w;
    }
    float* U = d_U + (h * NC + c) * (DH * DH);
#pragma unroll
    for (int r = 0; r < 4; r++)
        *(float4*)&U[(ty * 4 + r) * DH + tx * 4] = make_float4(acc[r][0], acc[r][1], acc[r][2], acc[r][3]);
}

__global__ void scan_kernel() {
    int e = blockIdx.x * blockDim.x + threadIdx.x;
    if (e >= H * DH * DH) return;
    int h = e >> 12;
    int idx = e & 4095;
    float gc = d_gpow[h * S + 64];
    float m = 0.0f;
    for (int c = 0; c < NC; c++) {
        d_M[(h * NC + c) * 4096 + idx] = m;
        m = gc * m + d_U[(h * NC + c) * 4096 + idx];
    }
}

__global__ void retn_kernel(const float* __restrict__ q, const float* __restrict__ k,
                            const float* __restrict__ v, float* __restrict__ ret) {
    __shared__ float qs[64][65];
    __shared__ float ks[32][65];
    __shared__ float vs[32][65];
    __shared__ float ss[64][33];

    int h = blockIdx.y;
    int cidx = blockIdx.x;
    int s0 = cidx * 64;
    int tid = threadIdx.x;

    for (int i = tid; i < 64 * 16; i += 256) {
        int r = i >> 4;
        int c4 = (i & 15) * 4;
        float4 t = *(const float4*)&q[(s0 + r) * D + h * DH + c4];
        qs[r][c4 + 0] = t.x; qs[r][c4 + 1] = t.y; qs[r][c4 + 2] = t.z; qs[r][c4 + 3] = t.w;
    }

    int aty = tid >> 4, atx = tid & 15;
    int bty = tid >> 4, btx = tid & 15;
    float acc[4][4] = {};
    const float* gp = d_gpow + h * S;
    const float* Mh = d_M + (h * NC + cidx) * (DH * DH);
    __syncthreads();

    for (int t = 0; t < 2; t++) {
        int m0 = s0 + t * 32;
        for (int i = tid; i < 32 * 16; i += 256) {
            int r = i >> 4;
            int c4 = (i & 15) * 4;
            float4 kv = *(const float4*)&k[(m0 + r) * D + h * DH + c4];
            ks[r][c4 + 0] = kv.x; ks[r][c4 + 1] = kv.y; ks[r][c4 + 2] = kv.z; ks[r][c4 + 3] = kv.w;
            float4 vv = *(const float4*)&v[(m0 + r) * D + h * DH + c4];
            vs[r][c4 + 0] = vv.x; vs[r][c4 + 1] = vv.y; vs[r][c4 + 2] = vv.z; vs[r][c4 + 3] = vv.w;
        }
        __syncthreads();

        float sv[4][2] = {};
#pragma unroll 16
        for (int d = 0; d < 64; d++) {
            float qr0 = qs[aty * 4 + 0][d];
            float qr1 = qs[aty * 4 + 1][d];
            float qr2 = qs[aty * 4 + 2][d];
            float qr3 = qs[aty * 4 + 3][d];
            float kc0 = ks[atx * 2 + 0][d];
            float kc1 = ks[atx * 2 + 1][d];
            sv[0][0] += qr0 * kc0; sv[0][1] += qr0 * kc1;
            sv[1][0] += qr1 * kc0; sv[1][1] += qr1 * kc1;
            sv[2][0] += qr2 * kc0; sv[2][1] += qr2 * kc1;
            sv[3][0] += qr3 * kc0; sv[3][1] += qr3 * kc1;
        }
#pragma unroll
        for (int r = 0; r < 4; r++)
#pragma unroll
            for (int c = 0; c < 2; c++) {
                int qi = s0 + aty * 4 + r;
                int kj = m0 + atx * 2 + c;
                int dist = qi - kj;
                ss[aty * 4 + r][atx * 2 + c] = (dist >= 0) ? sv[r][c] * gp[dist] : 0.0f;
            }
        __syncthreads();

#pragma unroll 8
        for (int j = 0; j < 32; j++) {
            float vr0 = vs[j][btx * 4 + 0];
            float vr1 = vs[j][btx * 4 + 1];
            float vr2 = vs[j][btx * 4 + 2];
            float vr3 = vs[j][btx * 4 + 3];
            float s0r = ss[bty * 4 + 0][j];
            float s1r = ss[bty * 4 + 1][j];
            float s2r = ss[bty * 4 + 2][j];
            float s3r = ss[bty * 4 + 3][j];
            acc[0][0] += s0r * vr0; acc[0][1] += s0r * vr1; acc[0][2] += s0r * vr2; acc[0][3] += s0r * vr3;
            acc[1][0] += s1r * vr0; acc[1][1] += s1r * vr1; acc[1][2] += s1r * vr2; acc[1][3] += s1r * vr3;
            acc[2][0] += s2r * vr0; acc[2][1] += s2r * vr1; acc[2][2] += s2r * vr2; acc[2][3] += s2r * vr3;
            acc[3][0] += s3r * vr0; acc[3][1] += s3r * vr1; acc[3][2] += s3r * vr2; acc[3][3] += s3r * vr3;
        }
        __syncthreads();
    }

    if (cidx > 0) {
        for (int t2 = 0; t2 < 2; t2++) {
            for (int i = tid; i < 32 * 16; i += 256) {
                int r = i >> 4;
                int c4 = (i & 15) * 4;
                float4 mv = *(const float4*)&Mh[(t2 * 32 + r) * DH + c4];
                vs[r][c4 + 0] = mv.x; vs[r][c4 + 1] = mv.y; vs[r][c4 + 2] = mv.z; vs[r][c4 + 3] = mv.w;
            }
            for (int i = tid; i < 64 * 32; i += 256) {
                int r = i >> 5;
                int j = i & 31;
                ss[r][j] = qs[r][t2 * 32 + j] * gp[r + 1];
            }
            __syncthreads();
#pragma unroll 8
            for (int j = 0; j < 32; j++) {
                float vr0 = vs[j][btx * 4 + 0];
                float vr1 = vs[j][btx * 4 + 1];
                float vr2 = vs[j][btx * 4 + 2];
                float vr3 = vs[j][btx * 4 + 3];
                float s0r = ss[bty * 4 + 0][j];
                float s1r = ss[bty * 4 + 1][j];
                float s2r = ss[bty * 4 + 2][j];
                float s3r = ss[bty * 4 + 3][j];
                acc[0][0] += s0r * vr0; acc[0][1] += s0r * vr1; acc[0][2] += s0r * vr2; acc[0][3] += s0r * vr3;
                acc[1][0] += s1r * vr0; acc[1][1] += s1r * vr1; acc[1][2] += s1r * vr2; acc[1][3] += s1r * vr3;
                acc[2][0] += s2r * vr0; acc[2][1] += s2r * vr1; acc[2][2] += s2r * vr2; acc[2][3] += s2r * vr3;
                acc[3][0] += s3r * vr0; acc[3][1] += s3r * vr1; acc[3][2] += s3r * vr2; acc[3][3] += s3r * vr3;
            }
            __syncthreads();
        }
    }

#pragma unroll
    for (int r = 0; r < 4; r++)
#pragma unroll
        for (int c = 0; c < 4; c++)
            qs[bty * 4 + r][btx * 4 + c] = acc[r][c];
    __syncthreads();

    if (tid < 64) {
        int i = tid;
        float mu = 0.0f;
#pragma unroll 16
        for (int d = 0; d < 64; d++) mu += qs[i][d];
        mu *= (1.0f / 64.0f);
        float var = 0.0f;
#pragma unroll 16
        for (int d = 0; d < 64; d++) {
            float dd = qs[i][d] - mu;
            var += dd * dd;
        }
        var *= (1.0f / 64.0f);
        float rs = rsqrtf(var + 1e-6f);
#pragma unroll 16
        for (int d = 0; d < 64; d++)
            ret[(s0 + i) * D + h * DH + d] = (qs[i][d] - mu) * rs;
    }
}

// ---------------- final ----------------
__global__ void final_kernel(const float* __restrict__ Wout, const float* __restrict__ bout,
                             float* __restrict__ out) {
    int row = blockIdx.x;
    int t = threadIdx.x;
    float s = 0.0f;
    for (int i = t; i < D; i += 64) s += d_x[row * D + i] * Wout[i];
    __shared__ float red[64];
    red[t] = s;
    __syncthreads();
    for (int o = 32; o > 0; o >>= 1) {
        if (t < o) red[t] += red[t + o];
        __syncthreads();
    }
    if (t == 0) out[row] = 1.0f / (1.0f + expf(-(red[0] + bout[0])));
}

// ---------------- host orchestration ----------------
extern "C" void kernel_launch(void* const* d_in, const int* in_sizes, int n_in,
                              void* d_out, int out_size) {
    const float* x_in  = (const float*)d_in[0];
    const float* pe    = (const float*)d_in[1];
    const float* Wq    = (const float*)d_in[2];
    const float* bq    = (const float*)d_in[3];
    const float* Wk    = (const float*)d_in[4];
    const float* bk    = (const float*)d_in[5];
    const float* Wv    = (const float*)d_in[6];
    const float* bv    = (const float*)d_in[7];
    const float* Wg    = (const float*)d_in[8];
    const float* bg    = (const float*)d_in[9];
    const float* Wo    = (const float*)d_in[10];
    const float* bo    = (const float*)d_in[11];
    const float* ln1w  = (const float*)d_in[12];
    const float* ln1b  = (const float*)d_in[13];
    const float* ln2w  = (const float*)d_in[14];
    const float* ln2b  = (const float*)d_in[15];
    const float* W1    = (const float*)d_in[16];
    const float* b1    = (const float*)d_in[17];
    const float* W2    = (const float*)d_in[18];
    const float* b2    = (const float*)d_in[19];
    const float* Wout  = (const float*)d_in[20];
    const float* bout  = (const float*)d_in[21];
    float* out = (float*)d_out;

    void* p;
    cudaGetSymbolAddress(&p, d_x);    float* px = (float*)p;
    cudaGetSymbolAddress(&p, d_q);    float* pq = (float*)p;
    cudaGetSymbolAddress(&p, d_k);    float* pk = (float*)p;
    cudaGetSymbolAddress(&p, d_v);    float* pv = (float*)p;
    cudaGetSymbolAddress(&p, d_ret);  float* pret = (float*)p;
    cudaGetSymbolAddress(&p, d_yh);   bf16* pyh = (bf16*)p;
    cudaGetSymbolAddress(&p, d_yl);   bf16* pyl = (bf16*)p;
    cudaGetSymbolAddress(&p, d_grh);  bf16* pgrh = (bf16*)p;
    cudaGetSymbolAddress(&p, d_grl);  bf16* pgrl = (bf16*)p;
    cudaGetSymbolAddress(&p, d_ffh);  bf16* pffh = (bf16*)p;
    cudaGetSymbolAddress(&p, d_ffl);  bf16* pffl = (bf16*)p;
    cudaGetSymbolAddress(&p, d_W5h);  bf16* pW5h = (bf16*)p;
    cudaGetSymbolAddress(&p, d_W5l);  bf16* pW5l = (bf16*)p;
    cudaGetSymbolAddress(&p, d_W1h);  bf16* pW1h = (bf16*)p;
    cudaGetSymbolAddress(&p, d_W1l);  bf16* pW1l = (bf16*)p;
    cudaGetSymbolAddress(&p, d_W2h);  bf16* pW2h = (bf16*)p;
    cudaGetSymbolAddress(&p, d_W2l);  bf16* pW2l = (bf16*)p;

    cudaFuncSetAttribute(qkvg_wmma,    cudaFuncAttributeMaxDynamicSharedMemorySize, SMEM_128);
    cudaFuncSetAttribute(ff1_wmma,     cudaFuncAttributeMaxDynamicSharedMemorySize, SMEM_128);
    cudaFuncSetAttribute(res_wmma<D>,  cudaFuncAttributeMaxDynamicSharedMemorySize, SMEM_64);
    cudaFuncSetAttribute(res_wmma<FF>, cudaFuncAttributeMaxDynamicSharedMemorySize, SMEM_64);

    init_tables_kernel<<<(S * 32 + 255) / 256, 256>>>();
    add_pos_kernel<<<(S * D + 255) / 256, 256>>>(x_in, pe);

    // weight splits
    {
        dim3 g5(DD / 256, 1, 20);
        wsplit5_kernel<<<g5, 256>>>(Wq, Wk, Wv, Wg, Wo, pW5h, pW5l);
        dim3 g1((D * FF) / 256, 1, L);
        wsplit_kernel<<<g1, 256>>>(W1, pW1h, pW1l, D * FF);
        wsplit_kernel<<<g1, 256>>>(W2, pW2h, pW2l, FF * D);
    }

    dim3 grid_qkvg(D / 128, S / 128, 4);   // 256 blocks
    dim3 grid_ff1(FF / 128, S / 128);      // 256 blocks
    dim3 grid_res(D / 128, S / 64);        // 128 blocks
    dim3 grid_ret(NC, H);                  // 256 blocks

    for (int l = 0; l < L; l++) {
        layernorm_split<<<S, 256>>>(px, ln1w + l * D, ln1b + l * D, 1e-5f);

        qkvg_wmma<<<grid_qkvg, 512, SMEM_128>>>(pyh, pyl,
            pW5h + (size_t)l * 5 * DD, pW5l + (size_t)l * 5 * DD,
            bq + l * D, bk + l * D, bv + l * D, bg + l * D);

        chunk_kv_kernel<<<grid_ret, 256>>>(pk, pv);
        scan_kernel<<<(H * DH * DH + 255) / 256, 256>>>();
        retn_kernel<<<grid_ret, 256>>>(pq, pk, pv, pret);

        mul_split_kernel<<<(S * D + 255) / 256, 256>>>();
        res_wmma<D><<<grid_res, 512, SMEM_64>>>(pgrh, pgrl,
            pW5h + ((size_t)l * 5 + 4) * DD, pW5l + ((size_t)l * 5 + 4) * DD, bo + l * D);

        layernorm_split<<<S, 256>>>(px, ln2w + l * D, ln2b + l * D, 1e-5f);
        ff1_wmma<<<grid_ff1, 512, SMEM_128>>>(pyh, pyl,
            pW1h + (size_t)l * D * FF, pW1l + (size_t)l * D * FF, b1 + l * FF);
        res_wmma<FF><<<grid_res, 512, SMEM_64>>>(pffh, pffl,
            pW2h + (size_t)l * FF * D, pW2l + (size_t)l * FF * D, b2 + l * D);
    }

    final_kernel<<<S, 64>>>(Wout, bout, out);
}

// round 15
// speedup vs baseline: 1.4038x; 1.0062x over previous
#include <cuda_runtime.h>
#include <cuda_bf16.h>
#include <mma.h>
#include <math.h>
#include <stdint.h>

using namespace nvcuda;
typedef __nv_bfloat16 bf16;

#define S 2048
#define D 512
#define H 8
#define DH 64
#define L 4
#define FF 2048
#define NC (S / 64)
#define DD (D * D)

// ---------------- scratch (static device globals; no allocation) ----------------
__device__ float d_x  [S * D];
__device__ float d_q  [S * D];
__device__ float d_k  [S * D];
__device__ float d_v  [S * D];
__device__ float d_g  [S * D];
__device__ float d_sin[S * (DH / 2)];
__device__ float d_cos[S * (DH / 2)];
__device__ float d_gpow[H * S];
__device__ float d_U[H * NC * DH * DH];
__device__ float d_M[H * NC * DH * DH];

__device__ __align__(16) bf16 d_yh [S * D];
__device__ __align__(16) bf16 d_yl [S * D];
__device__ __align__(16) bf16 d_grh[S * D];
__device__ __align__(16) bf16 d_grl[S * D];
__device__ __align__(16) bf16 d_ffh[S * FF];
__device__ __align__(16) bf16 d_ffl[S * FF];

// split weights, NATIVE [K][N] layout. slot l*5+t for {q,k,v,g,o}
__device__ __align__(16) bf16 d_W5h[20 * DD];
__device__ __align__(16) bf16 d_W5l[20 * DD];
__device__ __align__(16) bf16 d_W1h[4 * D * FF];   // [D][FF]
__device__ __align__(16) bf16 d_W1l[4 * D * FF];
__device__ __align__(16) bf16 d_W2h[4 * FF * D];   // [FF][D]
__device__ __align__(16) bf16 d_W2l[4 * FF * D];

// ---------------- helpers ----------------
__device__ __forceinline__ uint32_t smem_to_u32(const void* p) {
    uint32_t a;
    asm("{ .reg .u64 t; cvta.to.shared.u64 t, %1; cvt.u32.u64 %0, t; }" : "=r"(a) : "l"(p));
    return a;
}
__device__ __forceinline__ void cp16(uint32_t dst, const void* src) {
    asm volatile("cp.async.cg.shared.global [%0], [%1], 16;" :: "r"(dst), "l"(src));
}
#define CP_COMMIT() asm volatile("cp.async.commit_group;" ::: "memory")
#define CP_WAIT0()  asm volatile("cp.async.wait_group 0;" ::: "memory")
#define CP_WAIT1()  asm volatile("cp.async.wait_group 1;" ::: "memory")

// ---------------- setup tables ----------------
__global__ void init_tables_kernel() {
    int idx = blockIdx.x * blockDim.x + threadIdx.x;
    if (idx < S * (DH / 2)) {
        int s = idx / (DH / 2);
        int j = idx % (DH / 2);
        double theta = pow(10000.0, -(double)(2 * j) / (double)DH);
        double ang = (double)s * theta;
        d_sin[idx] = (float)sin(ang);
        d_cos[idx] = (float)cos(ang);
    }
    if (idx < H * S) {
        int h = idx / S;
        int dd = idx % S;
        double lg0 = log(1.0 / 32.0);
        double lg1 = log(1.0 / 512.0);
        double gamma = 1.0 - exp(lg0 + (lg1 - lg0) * (double)h / 7.0);
        d_gpow[idx] = (float)exp((double)dd * log(gamma));
    }
}

__global__ void add_pos_kernel(const float* __restrict__ x, const float* __restrict__ pe) {
    int i = blockIdx.x * blockDim.x + threadIdx.x;
    if (i < S * D) d_x[i] = x[i] + pe[i % D];
}

// ---------------- weight split: all 5 D*D families in one launch ----------------
__global__ void wsplit5_kernel(const float* __restrict__ Wq, const float* __restrict__ Wk,
                               const float* __restrict__ Wv, const float* __restrict__ Wg,
                               const float* __restrict__ Wo,
                               bf16* __restrict__ dh, bf16* __restrict__ dl) {
    int z = blockIdx.z;               // 0..19 = l*5+t
    int l = z / 5, t = z % 5;
    const float* src = (t == 0) ? Wq : (t == 1) ? Wk : (t == 2) ? Wv : (t == 3) ? Wg : Wo;
    int i = blockIdx.x * blockDim.x + threadIdx.x;
    float v = src[(size_t)l * DD + i];
    size_t o = (size_t)z * DD + i;
    bf16 h = __float2bfloat16(v);
    dh[o] = h;
    dl[o] = __float2bfloat16(v - __bfloat162float(h));
}

__global__ void wsplit_kernel(const float* __restrict__ src,
                              bf16* __restrict__ dh, bf16* __restrict__ dl, int n) {
    int z = blockIdx.z;
    int i = blockIdx.x * blockDim.x + threadIdx.x;
    if (i >= n) return;
    float v = src[(size_t)z * n + i];
    size_t o = (size_t)z * n + i;
    bf16 h = __float2bfloat16(v);
    dh[o] = h;
    dl[o] = __float2bfloat16(v - __bfloat162float(h));
}

// ---------------- layernorm -> bf16 hi/lo ----------------
__global__ void layernorm_split(const float* __restrict__ in,
                                const float* __restrict__ w, const float* __restrict__ b,
                                float eps) {
    int row = blockIdx.x;
    int t = threadIdx.x;
    const float* xr = in + row * D;
    __shared__ float red[256];
    float v0 = xr[t];
    float v1 = xr[t + 256];
    red[t] = v0 + v1;
    __syncthreads();
    for (int o = 128; o > 0; o >>= 1) { if (t < o) red[t] += red[t + o]; __syncthreads(); }
    float mu = red[0] * (1.0f / D);
    __syncthreads();
    float a0 = v0 - mu, a1 = v1 - mu;
    red[t] = a0 * a0 + a1 * a1;
    __syncthreads();
    for (int o = 128; o > 0; o >>= 1) { if (t < o) red[t] += red[t + o]; __syncthreads(); }
    float rstd = rsqrtf(red[0] * (1.0f / D) + eps);
    float o0 = a0 * rstd * w[t] + b[t];
    float o1 = a1 * rstd * w[t + 256] + b[t + 256];
    bf16 h0 = __float2bfloat16(o0);
    bf16 h1 = __float2bfloat16(o1);
    d_yh[row * D + t] = h0;
    d_yl[row * D + t] = __float2bfloat16(o0 - __bfloat162float(h0));
    d_yh[row * D + t + 256] = h1;
    d_yl[row * D + t + 256] = __float2bfloat16(o1 - __bfloat162float(h1));
}

// ================= wmma bf16 GEMM core (3-term compensation) =================
// BM in {128, 64}, BN=128, BK=64, 512 threads, 16 warps as 4x4.
// 3-stage cp.async pipeline (depth-2 prefetch).
#define ASTRIDE 72
#define BSTRIDE 136

template <int BM> struct CoreCfg {
    static constexpr int A_BYTES = BM * ASTRIDE * 2;
    static constexpr int B_BYTES = 64 * BSTRIDE * 2;       // 17408
    static constexpr int OFF_AL2 = A_BYTES;
    static constexpr int OFF_BH2 = 2 * A_BYTES;
    static constexpr int OFF_BL2 = 2 * A_BYTES + B_BYTES;
    static constexpr int BUF = 2 * A_BYTES + 2 * B_BYTES;
    static constexpr int MF = BM / 64;
};

template <int KDIM, int NDIM, int BM>
__device__ __forceinline__ void issue_chunk(const bf16* __restrict__ Ah,
                                            const bf16* __restrict__ Al,
                                            const bf16* __restrict__ Bh,
                                            const bf16* __restrict__ Bl,
                                            uint32_t bufbase, int row0, int col0,
                                            int kc, int tid) {
    using C = CoreCfg<BM>;
#pragma unroll
    for (int i = 0; i < BM / 64; i++) {
        int e = tid + i * 512;
        int r = e >> 3, c8 = (e & 7) * 8;
        uint32_t doff = (uint32_t)(r * ASTRIDE + c8) * 2;
        cp16(bufbase + doff, Ah + (size_t)(row0 + r) * KDIM + kc + c8);
        cp16(bufbase + C::OFF_AL2 + doff, Al + (size_t)(row0 + r) * KDIM + kc + c8);
    }
#pragma unroll
    for (int i = 0; i < 2; i++) {
        int e = tid + i * 512;
        int r = e >> 4, n8 = (e & 15) * 8;
        uint32_t doff = (uint32_t)(r * BSTRIDE + n8) * 2;
        cp16(bufbase + C::OFF_BH2 + doff, Bh + (size_t)(kc + r) * NDIM + col0 + n8);
        cp16(bufbase + C::OFF_BL2 + doff, Bl + (size_t)(kc + r) * NDIM + col0 + n8);
    }
    CP_COMMIT();
}

template <int KDIM, int NDIM, int BM>
__device__ __forceinline__ void wmma_core(const bf16* __restrict__ Ah,
                                          const bf16* __restrict__ Al,
                                          const bf16* __restrict__ Bh,
                                          const bf16* __restrict__ Bl,
                                          char* smem, int row0, int col0) {
    using C = CoreCfg<BM>;
    constexpr int MF = C::MF;
    constexpr int NCH = KDIM / 64;
    const int tid = threadIdx.x;
    const int warp = tid >> 5;
    const int wr = (warp >> 2) * (16 * MF);
    const int wc = (warp & 3) * 32;
    const uint32_t sb = smem_to_u32(smem);

    wmma::fragment<wmma::accumulator, 16, 16, 16, float> acc[MF][2];
#pragma unroll
    for (int m = 0; m < MF; m++)
#pragma unroll
        for (int n = 0; n < 2; n++) wmma::fill_fragment(acc[m][n], 0.0f);

    issue_chunk<KDIM, NDIM, BM>(Ah, Al, Bh, Bl, sb, row0, col0, 0, tid);
    if (NCH > 1)
        issue_chunk<KDIM, NDIM, BM>(Ah, Al, Bh, Bl, sb + C::BUF, row0, col0, 64, tid);

    int buf = 0;
    for (int c = 0; c < NCH; c++) {
        if (c + 1 < NCH) { CP_WAIT1(); } else { CP_WAIT0(); }
        __syncthreads();
        // prefetch chunk c+2 into the buffer freed by chunk c-1
        if (c + 2 < NCH) {
            int nb = buf + 2; if (nb >= 3) nb -= 3;
            issue_chunk<KDIM, NDIM, BM>(Ah, Al, Bh, Bl, sb + nb * C::BUF,
                                        row0, col0, (c + 2) * 64, tid);
        }

        const bf16* ash = (const bf16*)(smem + buf * C::BUF);
        const bf16* asl = (const bf16*)(smem + buf * C::BUF + C::OFF_AL2);
        const bf16* bsh = (const bf16*)(smem + buf * C::BUF + C::OFF_BH2);
        const bf16* bsl = (const bf16*)(smem + buf * C::BUF + C::OFF_BL2);

#pragma unroll
        for (int ks = 0; ks < 4; ks++) {
            wmma::fragment<wmma::matrix_a, 16, 16, 16, bf16, wmma::row_major> fa_h[MF], fa_l[MF];
            wmma::fragment<wmma::matrix_b, 16, 16, 16, bf16, wmma::row_major> fb_h[2], fb_l[2];
#pragma unroll
            for (int m = 0; m < MF; m++) {
                wmma::load_matrix_sync(fa_h[m], ash + (wr + m * 16) * ASTRIDE + ks * 16, ASTRIDE);
                wmma::load_matrix_sync(fa_l[m], asl + (wr + m * 16) * ASTRIDE + ks * 16, ASTRIDE);
            }
#pragma unroll
            for (int n = 0; n < 2; n++) {
                wmma::load_matrix_sync(fb_h[n], bsh + (ks * 16) * BSTRIDE + wc + n * 16, BSTRIDE);
                wmma::load_matrix_sync(fb_l[n], bsl + (ks * 16) * BSTRIDE + wc + n * 16, BSTRIDE);
            }
#pragma unroll
            for (int n = 0; n < 2; n++)
#pragma unroll
                for (int m = 0; m < MF; m++)
                    wmma::mma_sync(acc[m][n], fa_h[m], fb_h[n], acc[m][n]);
#pragma unroll
            for (int n = 0; n < 2; n++)
#pragma unroll
                for (int m = 0; m < MF; m++)
                    wmma::mma_sync(acc[m][n], fa_h[m], fb_l[n], acc[m][n]);
#pragma unroll
            for (int n = 0; n < 2; n++)
#pragma unroll
                for (int m = 0; m < MF; m++)
                    wmma::mma_sync(acc[m][n], fa_l[m], fb_h[n], acc[m][n]);
        }
        buf++; if (buf == 3) buf = 0;
    }

    // stage result into smem as f32 [BM][132]
    __syncthreads();
    float* stage = (float*)smem;
#pragma unroll
    for (int m = 0; m < MF; m++)
#pragma unroll
        for (int n = 0; n < 2; n++)
            wmma::store_matrix_sync(stage + (wr + m * 16) * 132 + wc + n * 16,
                                    acc[m][n], 132, wmma::mem_row_major);
    __syncthreads();
}

#define SMEM_128 (3 * CoreCfg<128>::BUF)   // 215040
#define SMEM_64  (3 * CoreCfg<64>::BUF)    // 159744

// ---- qkvg: z=0:q(rope*0.125) 1:k(rope) 2:v 3:g(silu); f32 outputs ----
__global__ void __launch_bounds__(512) qkvg_wmma(
    const bf16* __restrict__ Ah, const bf16* __restrict__ Al,
    const bf16* __restrict__ W5h, const bf16* __restrict__ W5l,
    const float* __restrict__ bq, const float* __restrict__ bk,
    const float* __restrict__ bv, const float* __restrict__ bg) {
    extern __shared__ char smem[];
    int tid = threadIdx.x;
    int z = blockIdx.z;
    int row0 = blockIdx.y * 128, col0 = blockIdx.x * 128;
    const bf16* Bh = W5h + (size_t)z * DD;
    const bf16* Bl = W5l + (size_t)z * DD;
    const float* bias = (z == 0) ? bq : (z == 1) ? bk : (z == 2) ? bv : bg;
    float* out = (z == 0) ? d_q : (z == 1) ? d_k : (z == 2) ? d_v : d_g;

    wmma_core<D, D, 128>(Ah, Al, Bh, Bl, smem, row0, col0);

    float (*st)[132] = (float (*)[132])smem;
    for (int i = tid; i < 4096; i += 512) {
        int r = i >> 5, c4 = (i & 31) * 4;
        int row = row0 + r, col = col0 + c4;
        float v0 = st[r][c4 + 0] + bias[col + 0];
        float v1 = st[r][c4 + 1] + bias[col + 1];
        float v2 = st[r][c4 + 2] + bias[col + 2];
        float v3 = st[r][c4 + 3] + bias[col + 3];
        float4 o;
        if (z <= 1) {
            int j = (col & 63) >> 1;
            float c0 = d_cos[row * 32 + j],     s0 = d_sin[row * 32 + j];
            float c1 = d_cos[row * 32 + j + 1], s1 = d_sin[row * 32 + j + 1];
            float sc = (z == 0) ? 0.125f : 1.0f;
            o.x = (v0 * c0 - v1 * s0) * sc;
            o.y = (v1 * c0 + v0 * s0) * sc;
            o.z = (v2 * c1 - v3 * s1) * sc;
            o.w = (v3 * c1 + v2 * s1) * sc;
        } else if (z == 2) {
            o = make_float4(v0, v1, v2, v3);
        } else {
            o.x = v0 / (1.0f + expf(-v0));
            o.y = v1 / (1.0f + expf(-v1));
            o.z = v2 / (1.0f + expf(-v2));
            o.w = v3 / (1.0f + expf(-v3));
        }
        *(float4*)&out[(size_t)row * D + col] = o;
    }
}

// ---- ffn1: SiLU -> bf16 hi/lo ----
__global__ void __launch_bounds__(512) ff1_wmma(
    const bf16* __restrict__ Ah, const bf16* __restrict__ Al,
    const bf16* __restrict__ Bh, const bf16* __restrict__ Bl,
    const float* __restrict__ bias) {
    extern __shared__ char smem[];
    int tid = threadIdx.x;
    int row0 = blockIdx.y * 128, col0 = blockIdx.x * 128;

    wmma_core<D, FF, 128>(Ah, Al, Bh, Bl, smem, row0, col0);

    float (*st)[132] = (float (*)[132])smem;
    for (int i = tid; i < 4096; i += 512) {
        int r = i >> 5, c4 = (i & 31) * 4;
        int row = row0 + r, col = col0 + c4;
        size_t o = (size_t)row * FF + col;
#pragma unroll
        for (int j2 = 0; j2 < 4; j2++) {
            float t = st[r][c4 + j2] + bias[col + j2];
            float v = t / (1.0f + expf(-t));
            bf16 h = __float2bfloat16(v);
            d_ffh[o + j2] = h;
            d_ffl[o + j2] = __float2bfloat16(v - __bfloat162float(h));
        }
    }
}

// ---- residual GEMM (BM=64): d_x += A@W + bias ----
template <int KDIM>
__global__ void __launch_bounds__(512) res_wmma(
    const bf16* __restrict__ Ah, const bf16* __restrict__ Al,
    const bf16* __restrict__ Bh, const bf16* __restrict__ Bl,
    const float* __restrict__ bias) {
    extern __shared__ char smem[];
    int tid = threadIdx.x;
    int row0 = blockIdx.y * 64, col0 = blockIdx.x * 128;

    wmma_core<KDIM, D, 64>(Ah, Al, Bh, Bl, smem, row0, col0);

    float (*st)[132] = (float (*)[132])smem;
    for (int i = tid; i < 2048; i += 512) {
        int r = i >> 5, c4 = (i & 31) * 4;
        int row = row0 + r, col = col0 + c4;
        float4 oldv = *(float4*)&d_x[(size_t)row * D + col];
        float4 o;
        o.x = st[r][c4 + 0] + bias[col + 0] + oldv.x;
        o.y = st[r][c4 + 1] + bias[col + 1] + oldv.y;
        o.z = st[r][c4 + 2] + bias[col + 2] + oldv.z;
        o.w = st[r][c4 + 3] + bias[col + 3] + oldv.w;
        *(float4*)&d_x[(size_t)row * D + col] = o;
    }
}

// ================= chunked retention =================
__global__ void chunk_kv_kernel(const float* __restrict__ k, const float* __restrict__ v) {
    __shared__ float ks[64][68];
    __shared__ float vs[64][68];
    int c = blockIdx.x, h = blockIdx.y;
    int s0 = c * 64;
    int tid = threadIdx.x;
    const float* gp = d_gpow + h * S;

    for (int i = tid; i < 64 * 16; i += 256) {
        int r = i >> 4;
        int c4 = (i & 15) * 4;
        float g = gp[63 - r];
        float4 kv = *(const float4*)&k[(s0 + r) * D + h * DH + c4];
        ks[r][c4 + 0] = kv.x * g; ks[r][c4 + 1] = kv.y * g;
        ks[r][c4 + 2] = kv.z * g; ks[r][c4 + 3] = kv.w * g;
        float4 vv = *(const float4*)&v[(s0 + r) * D + h * DH + c4];
        vs[r][c4 + 0] = vv.x; vs[r][c4 + 1] = vv.y;
        vs[r][c4 + 2] = vv.z; vs[r][c4 + 3] = vv.w;
    }
    __syncthreads();

    int tx = tid & 15, ty = tid >> 4;
    float acc[4][4] = {};
#pragma unroll 8
    for (int p = 0; p < 64; p++) {
        float4 a = *(const float4*)&ks[p][ty * 4];
        float4 b = *(const float4*)&vs[p][tx * 4];
        acc[0][0] += a.x * b.x; acc[0][1] += a.x * b.y; acc[0][2] += a.x * b.z; acc[0][3] += a.x * b.w;
        acc[1][0] += a.y * b.x; acc[1][1] += a.y * b.y; acc[1][2] += a.y * b.z; acc[1][3] += a.y * b.w;
        acc[2][0] += a.z * b.x; acc[2][1] += a.z * b.y; acc[2][2] += a.z * b.z; acc[2][3] += a.z * b.w;
        acc[3][0] += a.w * b.x; acc[3][1] += a.w * b.y; acc[3][2] += a.w * b.z; acc[3][3] += a.w * b.w;
    }
    float* U = d_U + (h * NC + c) * (DH * DH);
#pragma unroll
    for (int r = 0; r < 4; r++)
        *(float4*)&U[(ty * 4 + r) * DH + tx * 4] = make_float4(acc[r][0], acc[r][1], acc[r][2], acc[r][3]);
}

__global__ void scan_kernel() {
    int e = blockIdx.x * blockDim.x + threadIdx.x;
    if (e >= H * DH * DH) return;
    int h = e >> 12;
    int idx = e & 4095;
    float gc = d_gpow[h * S + 64];
    float m = 0.0f;
    for (int c = 0; c < NC; c++) {
        d_M[(h * NC + c) * 4096 + idx] = m;
        m = gc * m + d_U[(h * NC + c) * 4096 + idx];
    }
}

// retention + groupnorm + (g * ret) split fused
__global__ void retn_kernel(const float* __restrict__ q, const float* __restrict__ k,
                            const float* __restrict__ v) {
    __shared__ float qs[64][65];
    __shared__ float ks[32][65];
    __shared__ float vs[32][65];
    __shared__ float ss[64][33];

    int h = blockIdx.y;
    int cidx = blockIdx.x;
    int s0 = cidx * 64;
    int tid = threadIdx.x;

    for (int i = tid; i < 64 * 16; i += 256) {
        int r = i >> 4;
        int c4 = (i & 15) * 4;
        float4 t = *(const float4*)&q[(s0 + r) * D + h * DH + c4];
        qs[r][c4 + 0] = t.x; qs[r][c4 + 1] = t.y; qs[r][c4 + 2] = t.z; qs[r][c4 + 3] = t.w;
    }

    int aty = tid >> 4, atx = tid & 15;
    int bty = tid >> 4, btx = tid & 15;
    float acc[4][4] = {};
    const float* gp = d_gpow + h * S;
    const float* Mh = d_M + (h * NC + cidx) * (DH * DH);
    __syncthreads();

    for (int t = 0; t < 2; t++) {
        int m0 = s0 + t * 32;
        for (int i = tid; i < 32 * 16; i += 256) {
            int r = i >> 4;
            int c4 = (i & 15) * 4;
            float4 kv = *(const float4*)&k[(m0 + r) * D + h * DH + c4];
            ks[r][c4 + 0] = kv.x; ks[r][c4 + 1] = kv.y; ks[r][c4 + 2] = kv.z; ks[r][c4 + 3] = kv.w;
            float4 vv = *(const float4*)&v[(m0 + r) * D + h * DH + c4];
            vs[r][c4 + 0] = vv.x; vs[r][c4 + 1] = vv.y; vs[r][c4 + 2] = vv.z; vs[r][c4 + 3] = vv.w;
        }
        __syncthreads();

        float sv[4][2] = {};
#pragma unroll 16
        for (int d = 0; d < 64; d++) {
            float qr0 = qs[aty * 4 + 0][d];
            float qr1 = qs[aty * 4 + 1][d];
            float qr2 = qs[aty * 4 + 2][d];
            float qr3 = qs[aty * 4 + 3][d];
            float kc0 = ks[atx * 2 + 0][d];
            float kc1 = ks[atx * 2 + 1][d];
            sv[0][0] += qr0 * kc0; sv[0][1] += qr0 * kc1;
            sv[1][0] += qr1 * kc0; sv[1][1] += qr1 * kc1;
            sv[2][0] += qr2 * kc0; sv[2][1] += qr2 * kc1;
            sv[3][0] += qr3 * kc0; sv[3][1] += qr3 * kc1;
        }
#pragma unroll
        for (int r = 0; r < 4; r++)
#pragma unroll
            for (int c = 0; c < 2; c++) {
                int qi = s0 + aty * 4 + r;
                int kj = m0 + atx * 2 + c;
                int dist = qi - kj;
                ss[aty * 4 + r][atx * 2 + c] = (dist >= 0) ? sv[r][c] * gp[dist] : 0.0f;
            }
        __syncthreads();

#pragma unroll 8
        for (int j = 0; j < 32; j++) {
            float vr0 = vs[j][btx * 4 + 0];
            float vr1 = vs[j][btx * 4 + 1];
            float vr2 = vs[j][btx * 4 + 2];
            float vr3 = vs[j][btx * 4 + 3];
            float s0r = ss[bty * 4 + 0][j];
            float s1r = ss[bty * 4 + 1][j];
            float s2r = ss[bty * 4 + 2][j];
            float s3r = ss[bty * 4 + 3][j];
            acc[0][0] += s0r * vr0; acc[0][1] += s0r * vr1; acc[0][2] += s0r * vr2; acc[0][3] += s0r * vr3;
            acc[1][0] += s1r * vr0; acc[1][1] += s1r * vr1; acc[1][2] += s1r * vr2; acc[1][3] += s1r * vr3;
            acc[2][0] += s2r * vr0; acc[2][1] += s2r * vr1; acc[2][2] += s2r * vr2; acc[2][3] += s2r * vr3;
            acc[3][0] += s3r * vr0; acc[3][1] += s3r * vr1; acc[3][2] += s3r * vr2; acc[3][3] += s3r * vr3;
        }
        __syncthreads();
    }

    if (cidx > 0) {
        for (int t2 = 0; t2 < 2; t2++) {
            for (int i = tid; i < 32 * 16; i += 256) {
                int r = i >> 4;
                int c4 = (i & 15) * 4;
                float4 mv = *(const float4*)&Mh[(t2 * 32 + r) * DH + c4];
                vs[r][c4 + 0] = mv.x; vs[r][c4 + 1] = mv.y; vs[r][c4 + 2] = mv.z; vs[r][c4 + 3] = mv.w;
            }
            for (int i = tid; i < 64 * 32; i += 256) {
                int r = i >> 5;
                int j = i & 31;
                ss[r][j] = qs[r][t2 * 32 + j] * gp[r + 1];
            }
            __syncthreads();
#pragma unroll 8
            for (int j = 0; j < 32; j++) {
                float vr0 = vs[j][btx * 4 + 0];
                float vr1 = vs[j][btx * 4 + 1];
                float vr2 = vs[j][btx * 4 + 2];
                float vr3 = vs[j][btx * 4 + 3];
                float s0r = ss[bty * 4 + 0][j];
                float s1r = ss[bty * 4 + 1][j];
                float s2r = ss[bty * 4 + 2][j];
                float s3r = ss[bty * 4 + 3][j];
                acc[0][0] += s0r * vr0; acc[0][1] += s0r * vr1; acc[0][2] += s0r * vr2; acc[0][3] += s0r * vr3;
                acc[1][0] += s1r * vr0; acc[1][1] += s1r * vr1; acc[1][2] += s1r * vr2; acc[1][3] += s1r * vr3;
                acc[2][0] += s2r * vr0; acc[2][1] += s2r * vr1; acc[2][2] += s2r * vr2; acc[2][3] += s2r * vr3;
                acc[3][0] += s3r * vr0; acc[3][1] += s3r * vr1; acc[3][2] += s3r * vr2; acc[3][3] += s3r * vr3;
            }
            __syncthreads();
        }
    }

#pragma unroll
    for (int r = 0; r < 4; r++)
#pragma unroll
        for (int c = 0; c < 4; c++)
            qs[bty * 4 + r][btx * 4 + c] = acc[r][c];
    __syncthreads();

    if (tid < 64) {
        int i = tid;
        float mu = 0.0f;
#pragma unroll 16
        for (int d = 0; d < 64; d++) mu += qs[i][d];
        mu *= (1.0f / 64.0f);
        float var = 0.0f;
#pragma unroll 16
        for (int d = 0; d < 64; d++) {
            float dd = qs[i][d] - mu;
            var += dd * dd;
        }
        var *= (1.0f / 64.0f);
        float rs = rsqrtf(var + 1e-6f);
        size_t base = (size_t)(s0 + i) * D + h * DH;
#pragma unroll 16
        for (int d = 0; d < 64; d++) {
            float gv = d_g[base + d] * ((qs[i][d] - mu) * rs);
            bf16 hh = __float2bfloat16(gv);
            d_grh[base + d] = hh;
            d_grl[base + d] = __float2bfloat16(gv - __bfloat162float(hh));
        }
    }
}

// ---------------- final ----------------
__global__ void final_kernel(const float* __restrict__ Wout, const float* __restrict__ bout,
                             float* __restrict__ out) {
    int row = blockIdx.x;
    int t = threadIdx.x;
    float s = 0.0f;
    for (int i = t; i < D; i += 64) s += d_x[row * D + i] * Wout[i];
    __shared__ float red[64];
    red[t] = s;
    __syncthreads();
    for (int o = 32; o > 0; o >>= 1) {
        if (t < o) red[t] += red[t + o];
        __syncthreads();
    }
    if (t == 0) out[row] = 1.0f / (1.0f + expf(-(red[0] + bout[0])));
}

// ---------------- host orchestration ----------------
extern "C" void kernel_launch(void* const* d_in, const int* in_sizes, int n_in,
                              void* d_out, int out_size) {
    const float* x_in  = (const float*)d_in[0];
    const float* pe    = (const float*)d_in[1];
    const float* Wq    = (const float*)d_in[2];
    const float* bq    = (const float*)d_in[3];
    const float* Wk    = (const float*)d_in[4];
    const float* bk    = (const float*)d_in[5];
    const float* Wv    = (const float*)d_in[6];
    const float* bv    = (const float*)d_in[7];
    const float* Wg    = (const float*)d_in[8];
    const float* bg    = (const float*)d_in[9];
    const float* Wo    = (const float*)d_in[10];
    const float* bo    = (const float*)d_in[11];
    const float* ln1w  = (const float*)d_in[12];
    const float* ln1b  = (const float*)d_in[13];
    const float* ln2w  = (const float*)d_in[14];
    const float* ln2b  = (const float*)d_in[15];
    const float* W1    = (const float*)d_in[16];
    const float* b1    = (const float*)d_in[17];
    const float* W2    = (const float*)d_in[18];
    const float* b2    = (const float*)d_in[19];
    const float* Wout  = (const float*)d_in[20];
    const float* bout  = (const float*)d_in[21];
    float* out = (float*)d_out;

    void* p;
    cudaGetSymbolAddress(&p, d_x);    float* px = (float*)p;
    cudaGetSymbolAddress(&p, d_q);    float* pq = (float*)p;
    cudaGetSymbolAddress(&p, d_k);    float* pk = (float*)p;
    cudaGetSymbolAddress(&p, d_v);    float* pv = (float*)p;
    cudaGetSymbolAddress(&p, d_yh);   bf16* pyh = (bf16*)p;
    cudaGetSymbolAddress(&p, d_yl);   bf16* pyl = (bf16*)p;
    cudaGetSymbolAddress(&p, d_grh);  bf16* pgrh = (bf16*)p;
    cudaGetSymbolAddress(&p, d_grl);  bf16* pgrl = (bf16*)p;
    cudaGetSymbolAddress(&p, d_ffh);  bf16* pffh = (bf16*)p;
    cudaGetSymbolAddress(&p, d_ffl);  bf16* pffl = (bf16*)p;
    cudaGetSymbolAddress(&p, d_W5h);  bf16* pW5h = (bf16*)p;
    cudaGetSymbolAddress(&p, d_W5l);  bf16* pW5l = (bf16*)p;
    cudaGetSymbolAddress(&p, d_W1h);  bf16* pW1h = (bf16*)p;
    cudaGetSymbolAddress(&p, d_W1l);  bf16* pW1l = (bf16*)p;
    cudaGetSymbolAddress(&p, d_W2h);  bf16* pW2h = (bf16*)p;
    cudaGetSymbolAddress(&p, d_W2l);  bf16* pW2l = (bf16*)p;

    cudaFuncSetAttribute(qkvg_wmma,    cudaFuncAttributeMaxDynamicSharedMemorySize, SMEM_128);
    cudaFuncSetAttribute(ff1_wmma,     cudaFuncAttributeMaxDynamicSharedMemorySize, SMEM_128);
    cudaFuncSetAttribute(res_wmma<D>,  cudaFuncAttributeMaxDynamicSharedMemorySize, SMEM_64);
    cudaFuncSetAttribute(res_wmma<FF>, cudaFuncAttributeMaxDynamicSharedMemorySize, SMEM_64);

    init_tables_kernel<<<(S * 32 + 255) / 256, 256>>>();      // launch 1
    add_pos_kernel<<<(S * D + 255) / 256, 256>>>(x_in, pe);   // launch 2

    dim3 g5(DD / 256, 1, 20);
    wsplit5_kernel<<<g5, 256>>>(Wq, Wk, Wv, Wg, Wo, pW5h, pW5l);   // launch 3
    dim3 g1((D * FF) / 256, 1, L);
    wsplit_kernel<<<g1, 256>>>(W1, pW1h, pW1l, D * FF);            // launch 4

    dim3 grid_qkvg(D / 128, S / 128, 4);   // 256 blocks
    dim3 grid_ff1(FF / 128, S / 128);      // 256 blocks
    dim3 grid_res(D / 128, S / 64);        // 128 blocks
    dim3 grid_ret(NC, H);                  // 256 blocks

    for (int l = 0; l < L; l++) {
        layernorm_split<<<S, 256>>>(px, ln1w + l * D, ln1b + l * D, 1e-5f);  // launch 5 (l=0)

        qkvg_wmma<<<grid_qkvg, 512, SMEM_128>>>(pyh, pyl,                    // launch 6 (l=0): ncu target
            pW5h + (size_t)l * 5 * DD, pW5l + (size_t)l * 5 * DD,
            bq + l * D, bk + l * D, bv + l * D, bg + l * D);

        if (l == 0)
            wsplit_kernel<<<g1, 256>>>(W2, pW2h, pW2l, FF * D);   // deferred: first use is res_W2 below

        chunk_kv_kernel<<<grid_ret, 256>>>(pk, pv);
        scan_kernel<<<(H * DH * DH + 255) / 256, 256>>>();
        retn_kernel<<<grid_ret, 256>>>(pq, pk, pv);   // writes d_grh/d_grl (g*groupnorm fused)

        res_wmma<D><<<grid_res, 512, SMEM_64>>>(pgrh, pgrl,
            pW5h + ((size_t)l * 5 + 4) * DD, pW5l + ((size_t)l * 5 + 4) * DD, bo + l * D);

        layernorm_split<<<S, 256>>>(px, ln2w + l * D, ln2b + l * D, 1e-5f);
        ff1_wmma<<<grid_ff1, 512, SMEM_128>>>(pyh, pyl,
            pW1h + (size_t)l * D * FF, pW1l + (size_t)l * D * FF, b1 + l * FF);
        res_wmma<FF><<<grid_res, 512, SMEM_64>>>(pffh, pffl,
            pW2h + (size_t)l * FF * D, pW2l + (size_t)l * FF * D, b2 + l * D);
    }

    final_kernel<<<S, 64>>>(Wout, bout, out);
}

// round 16
// speedup vs baseline: 2.1796x; 1.5527x over previous
#include <cuda_runtime.h>
#include <cuda_fp16.h>
#include <mma.h>
#include <math.h>
#include <stdint.h>

using namespace nvcuda;

#define S 2048
#define D 512
#define H 8
#define DH 64
#define L 4
#define FF 2048
#define NC (S / 64)
#define DD (D * D)

// ---------------- scratch (static device globals; no allocation) ----------------
__device__ float d_x  [S * D];
__device__ float d_q  [S * D];
__device__ float d_k  [S * D];
__device__ float d_v  [S * D];
__device__ float d_g  [S * D];
__device__ float d_sin[S * (DH / 2)];
__device__ float d_cos[S * (DH / 2)];
__device__ float d_gpow[H * S];
__device__ float d_U[H * NC * DH * DH];
__device__ float d_M[H * NC * DH * DH];

// fp16 hi/lo activations
__device__ __align__(16) half d_yh [S * D];
__device__ __align__(16) half d_yl [S * D];
__device__ __align__(16) half d_grh[S * D];
__device__ __align__(16) half d_grl[S * D];
__device__ __align__(16) half d_ffh[S * FF];
__device__ __align__(16) half d_ffl[S * FF];

// single-fp16 weights, NATIVE [K][N] layout. slot l*5+t for {q,k,v,g,o}
__device__ __align__(16) half d_W5h[20 * DD];
__device__ __align__(16) half d_W1h[4 * D * FF];   // [D][FF]
__device__ __align__(16) half d_W2h[4 * FF * D];   // [FF][D]

// ---------------- helpers ----------------
__device__ __forceinline__ uint32_t smem_to_u32(const void* p) {
    uint32_t a;
    asm("{ .reg .u64 t; cvta.to.shared.u64 t, %1; cvt.u32.u64 %0, t; }" : "=r"(a) : "l"(p));
    return a;
}
__device__ __forceinline__ void cp16(uint32_t dst, const void* src) {
    asm volatile("cp.async.cg.shared.global [%0], [%1], 16;" :: "r"(dst), "l"(src));
}
#define CP_COMMIT() asm volatile("cp.async.commit_group;" ::: "memory")
#define CP_WAIT0()  asm volatile("cp.async.wait_group 0;" ::: "memory")
#define CP_WAIT1()  asm volatile("cp.async.wait_group 1;" ::: "memory")

// ---------------- setup tables ----------------
__global__ void init_tables_kernel() {
    int idx = blockIdx.x * blockDim.x + threadIdx.x;
    if (idx < S * (DH / 2)) {
        int s = idx / (DH / 2);
        int j = idx % (DH / 2);
        double theta = pow(10000.0, -(double)(2 * j) / (double)DH);
        double ang = (double)s * theta;
        d_sin[idx] = (float)sin(ang);
        d_cos[idx] = (float)cos(ang);
    }
    if (idx < H * S) {
        int h = idx / S;
        int dd = idx % S;
        double lg0 = log(1.0 / 32.0);
        double lg1 = log(1.0 / 512.0);
        double gamma = 1.0 - exp(lg0 + (lg1 - lg0) * (double)h / 7.0);
        d_gpow[idx] = (float)exp((double)dd * log(gamma));
    }
}

__global__ void add_pos_kernel(const float* __restrict__ x, const float* __restrict__ pe) {
    int i = blockIdx.x * blockDim.x + threadIdx.x;
    if (i < S * D) d_x[i] = x[i] + pe[i % D];
}

// ---------------- weight convert (single fp16, layout preserved) ----------------
__global__ void wconv5_kernel(const float* __restrict__ Wq, const float* __restrict__ Wk,
                              const float* __restrict__ Wv, const float* __restrict__ Wg,
                              const float* __restrict__ Wo, half* __restrict__ dh) {
    int z = blockIdx.z;               // 0..19 = l*5+t
    int l = z / 5, t = z % 5;
    const float* src = (t == 0) ? Wq : (t == 1) ? Wk : (t == 2) ? Wv : (t == 3) ? Wg : Wo;
    int i = blockIdx.x * blockDim.x + threadIdx.x;
    dh[(size_t)z * DD + i] = __float2half(src[(size_t)l * DD + i]);
}

__global__ void wconv_kernel(const float* __restrict__ src, half* __restrict__ dh, int n) {
    int z = blockIdx.z;
    int i = blockIdx.x * blockDim.x + threadIdx.x;
    if (i >= n) return;
    dh[(size_t)z * n + i] = __float2half(src[(size_t)z * n + i]);
}

// ---------------- layernorm -> fp16 hi/lo ----------------
__global__ void layernorm_split(const float* __restrict__ in,
                                const float* __restrict__ w, const float* __restrict__ b,
                                float eps) {
    int row = blockIdx.x;
    int t = threadIdx.x;
    const float* xr = in + row * D;
    __shared__ float red[256];
    float v0 = xr[t];
    float v1 = xr[t + 256];
    red[t] = v0 + v1;
    __syncthreads();
    for (int o = 128; o > 0; o >>= 1) { if (t < o) red[t] += red[t + o]; __syncthreads(); }
    float mu = red[0] * (1.0f / D);
    __syncthreads();
    float a0 = v0 - mu, a1 = v1 - mu;
    red[t] = a0 * a0 + a1 * a1;
    __syncthreads();
    for (int o = 128; o > 0; o >>= 1) { if (t < o) red[t] += red[t + o]; __syncthreads(); }
    float rstd = rsqrtf(red[0] * (1.0f / D) + eps);
    float o0 = a0 * rstd * w[t] + b[t];
    float o1 = a1 * rstd * w[t + 256] + b[t + 256];
    half h0 = __float2half(o0);
    half h1 = __float2half(o1);
    d_yh[row * D + t] = h0;
    d_yl[row * D + t] = __float2half(o0 - __half2float(h0));
    d_yh[row * D + t + 256] = h1;
    d_yl[row * D + t + 256] = __float2half(o1 - __half2float(h1));
}

// ================= wmma fp16 GEMM core (A split 2-term compensation) =============
// BM in {128, 64}, BN=128, BK=64, 512 threads, 16 warps as 4x4.
// 3-stage cp.async pipeline. smem buffer = Ah | Al | B.
#define ASTRIDE 72
#define BSTRIDE 136

template <int BM> struct CoreCfg {
    static constexpr int A_BYTES = BM * ASTRIDE * 2;
    static constexpr int B_BYTES = 64 * BSTRIDE * 2;       // 17408
    static constexpr int OFF_AL2 = A_BYTES;
    static constexpr int OFF_B2  = 2 * A_BYTES;
    static constexpr int BUF = 2 * A_BYTES + B_BYTES;
    static constexpr int MF = BM / 64;
};

template <int KDIM, int NDIM, int BM>
__device__ __forceinline__ void issue_chunk(const half* __restrict__ Ah,
                                            const half* __restrict__ Al,
                                            const half* __restrict__ B,
                                            uint32_t bufbase, int row0, int col0,
                                            int kc, int tid) {
    using C = CoreCfg<BM>;
#pragma unroll
    for (int i = 0; i < BM / 64; i++) {
        int e = tid + i * 512;
        int r = e >> 3, c8 = (e & 7) * 8;
        uint32_t doff = (uint32_t)(r * ASTRIDE + c8) * 2;
        cp16(bufbase + doff, Ah + (size_t)(row0 + r) * KDIM + kc + c8);
        cp16(bufbase + C::OFF_AL2 + doff, Al + (size_t)(row0 + r) * KDIM + kc + c8);
    }
#pragma unroll
    for (int i = 0; i < 2; i++) {
        int e = tid + i * 512;
        int r = e >> 4, n8 = (e & 15) * 8;
        uint32_t doff = (uint32_t)(r * BSTRIDE + n8) * 2;
        cp16(bufbase + C::OFF_B2 + doff, B + (size_t)(kc + r) * NDIM + col0 + n8);
    }
    CP_COMMIT();
}

template <int KDIM, int NDIM, int BM>
__device__ __forceinline__ void wmma_core(const half* __restrict__ Ah,
                                          const half* __restrict__ Al,
                                          const half* __restrict__ B,
                                          char* smem, int row0, int col0) {
    using C = CoreCfg<BM>;
    constexpr int MF = C::MF;
    constexpr int NCH = KDIM / 64;
    const int tid = threadIdx.x;
    const int warp = tid >> 5;
    const int wr = (warp >> 2) * (16 * MF);
    const int wc = (warp & 3) * 32;
    const uint32_t sb = smem_to_u32(smem);

    wmma::fragment<wmma::accumulator, 16, 16, 16, float> acc[MF][2];
#pragma unroll
    for (int m = 0; m < MF; m++)
#pragma unroll
        for (int n = 0; n < 2; n++) wmma::fill_fragment(acc[m][n], 0.0f);

    issue_chunk<KDIM, NDIM, BM>(Ah, Al, B, sb, row0, col0, 0, tid);
    if (NCH > 1)
        issue_chunk<KDIM, NDIM, BM>(Ah, Al, B, sb + C::BUF, row0, col0, 64, tid);

    int buf = 0;
    for (int c = 0; c < NCH; c++) {
        if (c + 1 < NCH) { CP_WAIT1(); } else { CP_WAIT0(); }
        __syncthreads();
        if (c + 2 < NCH) {
            int nb = buf + 2; if (nb >= 3) nb -= 3;
            issue_chunk<KDIM, NDIM, BM>(Ah, Al, B, sb + nb * C::BUF,
                                        row0, col0, (c + 2) * 64, tid);
        }

        const half* ash = (const half*)(smem + buf * C::BUF);
        const half* asl = (const half*)(smem + buf * C::BUF + C::OFF_AL2);
        const half* bs  = (const half*)(smem + buf * C::BUF + C::OFF_B2);

#pragma unroll
        for (int ks = 0; ks < 4; ks++) {
            wmma::fragment<wmma::matrix_a, 16, 16, 16, half, wmma::row_major> fa_h[MF], fa_l[MF];
            wmma::fragment<wmma::matrix_b, 16, 16, 16, half, wmma::row_major> fb[2];
#pragma unroll
            for (int m = 0; m < MF; m++) {
                wmma::load_matrix_sync(fa_h[m], ash + (wr + m * 16) * ASTRIDE + ks * 16, ASTRIDE);
                wmma::load_matrix_sync(fa_l[m], asl + (wr + m * 16) * ASTRIDE + ks * 16, ASTRIDE);
            }
#pragma unroll
            for (int n = 0; n < 2; n++)
                wmma::load_matrix_sync(fb[n], bs + (ks * 16) * BSTRIDE + wc + n * 16, BSTRIDE);
            // term-major: hi term then lo term (max acc-reuse distance)
#pragma unroll
            for (int n = 0; n < 2; n++)
#pragma unroll
                for (int m = 0; m < MF; m++)
                    wmma::mma_sync(acc[m][n], fa_h[m], fb[n], acc[m][n]);
#pragma unroll
            for (int n = 0; n < 2; n++)
#pragma unroll
                for (int m = 0; m < MF; m++)
                    wmma::mma_sync(acc[m][n], fa_l[m], fb[n], acc[m][n]);
        }
        buf++; if (buf == 3) buf = 0;
    }

    // stage result into smem as f32 [BM][132]
    __syncthreads();
    float* stage = (float*)smem;
#pragma unroll
    for (int m = 0; m < MF; m++)
#pragma unroll
        for (int n = 0; n < 2; n++)
            wmma::store_matrix_sync(stage + (wr + m * 16) * 132 + wc + n * 16,
                                    acc[m][n], 132, wmma::mem_row_major);
    __syncthreads();
}

#define SMEM_128 (3 * CoreCfg<128>::BUF)   // 162816
#define SMEM_64  (3 * CoreCfg<64>::BUF)    // 107520

// ---- qkvg: z=0:q(rope*0.125) 1:k(rope) 2:v 3:g(silu); f32 outputs ----
__global__ void __launch_bounds__(512) qkvg_wmma(
    const half* __restrict__ Ah, const half* __restrict__ Al,
    const half* __restrict__ W5, 
    const float* __restrict__ bq, const float* __restrict__ bk,
    const float* __restrict__ bv, const float* __restrict__ bg) {
    extern __shared__ char smem[];
    int tid = threadIdx.x;
    int z = blockIdx.z;
    int row0 = blockIdx.y * 128, col0 = blockIdx.x * 128;
    const half* B = W5 + (size_t)z * DD;
    const float* bias = (z == 0) ? bq : (z == 1) ? bk : (z == 2) ? bv : bg;
    float* out = (z == 0) ? d_q : (z == 1) ? d_k : (z == 2) ? d_v : d_g;

    wmma_core<D, D, 128>(Ah, Al, B, smem, row0, col0);

    float (*st)[132] = (float (*)[132])smem;
    for (int i = tid; i < 4096; i += 512) {
        int r = i >> 5, c4 = (i & 31) * 4;
        int row = row0 + r, col = col0 + c4;
        float v0 = st[r][c4 + 0] + bias[col + 0];
        float v1 = st[r][c4 + 1] + bias[col + 1];
        float v2 = st[r][c4 + 2] + bias[col + 2];
        float v3 = st[r][c4 + 3] + bias[col + 3];
        float4 o;
        if (z <= 1) {
            int j = (col & 63) >> 1;
            float c0 = d_cos[row * 32 + j],     s0 = d_sin[row * 32 + j];
            float c1 = d_cos[row * 32 + j + 1], s1 = d_sin[row * 32 + j + 1];
            float sc = (z == 0) ? 0.125f : 1.0f;
            o.x = (v0 * c0 - v1 * s0) * sc;
            o.y = (v1 * c0 + v0 * s0) * sc;
            o.z = (v2 * c1 - v3 * s1) * sc;
            o.w = (v3 * c1 + v2 * s1) * sc;
        } else if (z == 2) {
            o = make_float4(v0, v1, v2, v3);
        } else {
            o.x = v0 / (1.0f + expf(-v0));
            o.y = v1 / (1.0f + expf(-v1));
            o.z = v2 / (1.0f + expf(-v2));
            o.w = v3 / (1.0f + expf(-v3));
        }
        *(float4*)&out[(size_t)row * D + col] = o;
    }
}

// ---- ffn1: SiLU -> fp16 hi/lo ----
__global__ void __launch_bounds__(512) ff1_wmma(
    const half* __restrict__ Ah, const half* __restrict__ Al,
    const half* __restrict__ B, const float* __restrict__ bias) {
    extern __shared__ char smem[];
    int tid = threadIdx.x;
    int row0 = blockIdx.y * 128, col0 = blockIdx.x * 128;

    wmma_core<D, FF, 128>(Ah, Al, B, smem, row0, col0);

    float (*st)[132] = (float (*)[132])smem;
    for (int i = tid; i < 4096; i += 512) {
        int r = i >> 5, c4 = (i & 31) * 4;
        int row = row0 + r, col = col0 + c4;
        size_t o = (size_t)row * FF + col;
#pragma unroll
        for (int j2 = 0; j2 < 4; j2++) {
            float t = st[r][c4 + j2] + bias[col + j2];
            float v = t / (1.0f + expf(-t));
            half h = __float2half(v);
            d_ffh[o + j2] = h;
            d_ffl[o + j2] = __float2half(v - __half2float(h));
        }
    }
}

// ---- residual GEMM (BM=64): d_x += A@W + bias ----
template <int KDIM>
__global__ void __launch_bounds__(512) res_wmma(
    const half* __restrict__ Ah, const half* __restrict__ Al,
    const half* __restrict__ B, const float* __restrict__ bias) {
    extern __shared__ char smem[];
    int tid = threadIdx.x;
    int row0 = blockIdx.y * 64, col0 = blockIdx.x * 128;

    wmma_core<KDIM, D, 64>(Ah, Al, B, smem, row0, col0);

    float (*st)[132] = (float (*)[132])smem;
    for (int i = tid; i < 2048; i += 512) {
        int r = i >> 5, c4 = (i & 31) * 4;
        int row = row0 + r, col = col0 + c4;
        float4 oldv = *(float4*)&d_x[(size_t)row * D + col];
        float4 o;
        o.x = st[r][c4 + 0] + bias[col + 0] + oldv.x;
        o.y = st[r][c4 + 1] + bias[col + 1] + oldv.y;
        o.z = st[r][c4 + 2] + bias[col + 2] + oldv.z;
        o.w = st[r][c4 + 3] + bias[col + 3] + oldv.w;
        *(float4*)&d_x[(size_t)row * D + col] = o;
    }
}

// ================= chunked retention =================
__global__ void chunk_kv_kernel(const float* __restrict__ k, const float* __restrict__ v) {
    __shared__ float ks[64][68];
    __shared__ float vs[64][68];
    int c = blockIdx.x, h = blockIdx.y;
    int s0 = c * 64;
    int tid = threadIdx.x;
    const float* gp = d_gpow + h * S;

    for (int i = tid; i < 64 * 16; i += 256) {
        int r = i >> 4;
        int c4 = (i & 15) * 4;
        float g = gp[63 - r];
        float4 kv = *(const float4*)&k[(s0 + r) * D + h * DH + c4];
        ks[r][c4 + 0] = kv.x * g; ks[r][c4 + 1] = kv.y * g;
        ks[r][c4 + 2] = kv.z * g; ks[r][c4 + 3] = kv.w * g;
        float4 vv = *(const float4*)&v[(s0 + r) * D + h * DH + c4];
        vs[r][c4 + 0] = vv.x; vs[r][c4 + 1] = vv.y;
        vs[r][c4 + 2] = vv.z; vs[r][c4 + 3] = vv.w;
    }
    __syncthreads();

    int tx = tid & 15, ty = tid >> 4;
    float acc[4][4] = {};
#pragma unroll 8
    for (int p = 0; p < 64; p++) {
        float4 a = *(const float4*)&ks[p][ty * 4];
        float4 b = *(const float4*)&vs[p][tx * 4];
        acc[0][0] += a.x * b.x; acc[0][1] += a.x * b.y; acc[0][2] += a.x * b.z; acc[0][3] += a.x * b.w;
        acc[1][0] += a.y * b.x; acc[1][1] += a.y * b.y; acc[1][2] += a.y * b.z; acc[1][3] += a.y * b.w;
        acc[2][0] += a.z * b.x; acc[2][1] += a.z * b.y; acc[2][2] += a.z * b.z; acc[2][3] += a.z * b.w;
        acc[3][0] += a.w * b.x; acc[3][1] += a.w * b.y; acc[3][2] += a.w * b.z; acc[3][3] += a.w * b.w;
    }
    float* U = d_U + (h * NC + c) * (DH * DH);
#pragma unroll
    for (int r = 0; r < 4; r++)
        *(float4*)&U[(ty * 4 + r) * DH + tx * 4] = make_float4(acc[r][0], acc[r][1], acc[r][2], acc[r][3]);
}

__global__ void scan_kernel() {
    int e = blockIdx.x * blockDim.x + threadIdx.x;
    if (e >= H * DH * DH) return;
    int h = e >> 12;
    int idx = e & 4095;
    float gc = d_gpow[h * S + 64];
    float m = 0.0f;
    for (int c = 0; c < NC; c++) {
        d_M[(h * NC + c) * 4096 + idx] = m;
        m = gc * m + d_U[(h * NC + c) * 4096 + idx];
    }
}

// retention + groupnorm + (g * ret) fp16 split fused
__global__ void retn_kernel(const float* __restrict__ q, const float* __restrict__ k,
                            const float* __restrict__ v) {
    __shared__ float qs[64][65];
    __shared__ float ks[32][65];
    __shared__ float vs[32][65];
    __shared__ float ss[64][33];

    int h = blockIdx.y;
    int cidx = blockIdx.x;
    int s0 = cidx * 64;
    int tid = threadIdx.x;

    for (int i = tid; i < 64 * 16; i += 256) {
        int r = i >> 4;
        int c4 = (i & 15) * 4;
        float4 t = *(const float4*)&q[(s0 + r) * D + h * DH + c4];
        qs[r][c4 + 0] = t.x; qs[r][c4 + 1] = t.y; qs[r][c4 + 2] = t.z; qs[r][c4 + 3] = t.w;
    }

    int aty = tid >> 4, atx = tid & 15;
    int bty = tid >> 4, btx = tid & 15;
    float acc[4][4] = {};
    const float* gp = d_gpow + h * S;
    const float* Mh = d_M + (h * NC + cidx) * (DH * DH);
    __syncthreads();

    for (int t = 0; t < 2; t++) {
        int m0 = s0 + t * 32;
        for (int i = tid; i < 32 * 16; i += 256) {
            int r = i >> 4;
            int c4 = (i & 15) * 4;
            float4 kv = *(const float4*)&k[(m0 + r) * D + h * DH + c4];
            ks[r][c4 + 0] = kv.x; ks[r][c4 + 1] = kv.y; ks[r][c4 + 2] = kv.z; ks[r][c4 + 3] = kv.w;
            float4 vv = *(const float4*)&v[(m0 + r) * D + h * DH + c4];
            vs[r][c4 + 0] = vv.x; vs[r][c4 + 1] = vv.y; vs[r][c4 + 2] = vv.z; vs[r][c4 + 3] = vv.w;
        }
        __syncthreads();

        float sv[4][2] = {};
#pragma unroll 16
        for (int d = 0; d < 64; d++) {
            float qr0 = qs[aty * 4 + 0][d];
            float qr1 = qs[aty * 4 + 1][d];
            float qr2 = qs[aty * 4 + 2][d];
            float qr3 = qs[aty * 4 + 3][d];
            float kc0 = ks[atx * 2 + 0][d];
            float kc1 = ks[atx * 2 + 1][d];
            sv[0][0] += qr0 * kc0; sv[0][1] += qr0 * kc1;
            sv[1][0] += qr1 * kc0; sv[1][1] += qr1 * kc1;
            sv[2][0] += qr2 * kc0; sv[2][1] += qr2 * kc1;
            sv[3][0] += qr3 * kc0; sv[3][1] += qr3 * kc1;
        }
#pragma unroll
        for (int r = 0; r < 4; r++)
#pragma unroll
            for (int c = 0; c < 2; c++) {
                int qi = s0 + aty * 4 + r;
                int kj = m0 + atx * 2 + c;
                int dist = qi - kj;
                ss[aty * 4 + r][atx * 2 + c] = (dist >= 0) ? sv[r][c] * gp[dist] : 0.0f;
            }
        __syncthreads();

#pragma unroll 8
        for (int j = 0; j < 32; j++) {
            float vr0 = vs[j][btx * 4 + 0];
            float vr1 = vs[j][btx * 4 + 1];
            float vr2 = vs[j][btx * 4 + 2];
            float vr3 = vs[j][btx * 4 + 3];
            float s0r = ss[bty * 4 + 0][j];
            float s1r = ss[bty * 4 + 1][j];
            float s2r = ss[bty * 4 + 2][j];
            float s3r = ss[bty * 4 + 3][j];
            acc[0][0] += s0r * vr0; acc[0][1] += s0r * vr1; acc[0][2] += s0r * vr2; acc[0][3] += s0r * vr3;
            acc[1][0] += s1r * vr0; acc[1][1] += s1r * vr1; acc[1][2] += s1r * vr2; acc[1][3] += s1r * vr3;
            acc[2][0] += s2r * vr0; acc[2][1] += s2r * vr1; acc[2][2] += s2r * vr2; acc[2][3] += s2r * vr3;
            acc[3][0] += s3r * vr0; acc[3][1] += s3r * vr1; acc[3][2] += s3r * vr2; acc[3][3] += s3r * vr3;
        }
        __syncthreads();
    }

    if (cidx > 0) {
        for (int t2 = 0; t2 < 2; t2++) {
            for (int i = tid; i < 32 * 16; i += 256) {
                int r = i >> 4;
                int c4 = (i & 15) * 4;
                float4 mv = *(const float4*)&Mh[(t2 * 32 + r) * DH + c4];
                vs[r][c4 + 0] = mv.x; vs[r][c4 + 1] = mv.y; vs[r][c4 + 2] = mv.z; vs[r][c4 + 3] = mv.w;
            }
            for (int i = tid; i < 64 * 32; i += 256) {
                int r = i >> 5;
                int j = i & 31;
                ss[r][j] = qs[r][t2 * 32 + j] * gp[r + 1];
            }
            __syncthreads();
#pragma unroll 8
            for (int j = 0; j < 32; j++) {
                float vr0 = vs[j][btx * 4 + 0];
                float vr1 = vs[j][btx * 4 + 1];
                float vr2 = vs[j][btx * 4 + 2];
                float vr3 = vs[j][btx * 4 + 3];
                float s0r = ss[bty * 4 + 0][j];
                float s1r = ss[bty * 4 + 1][j];
                float s2r = ss[bty * 4 + 2][j];
                float s3r = ss[bty * 4 + 3][j];
                acc[0][0] += s0r * vr0; acc[0][1] += s0r * vr1; acc[0][2] += s0r * vr2; acc[0][3] += s0r * vr3;
                acc[1][0] += s1r * vr0; acc[1][1] += s1r * vr1; acc[1][2] += s1r * vr2; acc[1][3] += s1r * vr3;
                acc[2][0] += s2r * vr0; acc[2][1] += s2r * vr1; acc[2][2] += s2r * vr2; acc[2][3] += s2r * vr3;
                acc[3][0] += s3r * vr0; acc[3][1] += s3r * vr1; acc[3][2] += s3r * vr2; acc[3][3] += s3r * vr3;
            }
            __syncthreads();
        }
    }

#pragma unroll
    for (int r = 0; r < 4; r++)
#pragma unroll
        for (int c = 0; c < 4; c++)
            qs[bty * 4 + r][btx * 4 + c] = acc[r][c];
    __syncthreads();

    if (tid < 64) {
        int i = tid;
        float mu = 0.0f;
#pragma unroll 16
        for (int d = 0; d < 64; d++) mu += qs[i][d];
        mu *= (1.0f / 64.0f);
        float var = 0.0f;
#pragma unroll 16
        for (int d = 0; d < 64; d++) {
            float dd = qs[i][d] - mu;
            var += dd * dd;
        }
        var *= (1.0f / 64.0f);
        float rs = rsqrtf(var + 1e-6f);
        size_t base = (size_t)(s0 + i) * D + h * DH;
#pragma unroll 16
        for (int d = 0; d < 64; d++) {
            float gv = d_g[base + d] * ((qs[i][d] - mu) * rs);
            half hh = __float2half(gv);
            d_grh[base + d] = hh;
            d_grl[base + d] = __float2half(gv - __half2float(hh));
        }
    }
}

// ---------------- final ----------------
__global__ void final_kernel(const float* __restrict__ Wout, const float* __restrict__ bout,
                             float* __restrict__ out) {
    int row = blockIdx.x;
    int t = threadIdx.x;
    float s = 0.0f;
    for (int i = t; i < D; i += 64) s += d_x[row * D + i] * Wout[i];
    __shared__ float red[64];
    red[t] = s;
    __syncthreads();
    for (int o = 32; o > 0; o >>= 1) {
        if (t < o) red[t] += red[t + o];
        __syncthreads();
    }
    if (t == 0) out[row] = 1.0f / (1.0f + expf(-(red[0] + bout[0])));
}

// ---------------- host orchestration ----------------
extern "C" void kernel_launch(void* const* d_in, const int* in_sizes, int n_in,
                              void* d_out, int out_size) {
    const float* x_in  = (const float*)d_in[0];
    const float* pe    = (const float*)d_in[1];
    const float* Wq    = (const float*)d_in[2];
    const float* bq    = (const float*)d_in[3];
    const float* Wk    = (const float*)d_in[4];
    const float* bk    = (const float*)d_in[5];
    const float* Wv    = (const float*)d_in[6];
    const float* bv    = (const float*)d_in[7];
    const float* Wg    = (const float*)d_in[8];
    const float* bg    = (const float*)d_in[9];
    const float* Wo    = (const float*)d_in[10];
    const float* bo    = (const float*)d_in[11];
    const float* ln1w  = (const float*)d_in[12];
    const float* ln1b  = (const float*)d_in[13];
    const float* ln2w  = (const float*)d_in[14];
    const float* ln2b  = (const float*)d_in[15];
    const float* W1    = (const float*)d_in[16];
    const float* b1    = (const float*)d_in[17];
    const float* W2    = (const float*)d_in[18];
    const float* b2    = (const float*)d_in[19];
    const float* Wout  = (const float*)d_in[20];
    const float* bout  = (const float*)d_in[21];
    float* out = (float*)d_out;

    void* p;
    cudaGetSymbolAddress(&p, d_x);    float* px = (float*)p;
    cudaGetSymbolAddress(&p, d_q);    float* pq = (float*)p;
    cudaGetSymbolAddress(&p, d_k);    float* pk = (float*)p;
    cudaGetSymbolAddress(&p, d_v);    float* pv = (float*)p;
    cudaGetSymbolAddress(&p, d_yh);   half* pyh = (half*)p;
    cudaGetSymbolAddress(&p, d_yl);   half* pyl = (half*)p;
    cudaGetSymbolAddress(&p, d_grh);  half* pgrh = (half*)p;
    cudaGetSymbolAddress(&p, d_grl);  half* pgrl = (half*)p;
    cudaGetSymbolAddress(&p, d_ffh);  half* pffh = (half*)p;
    cudaGetSymbolAddress(&p, d_ffl);  half* pffl = (half*)p;
    cudaGetSymbolAddress(&p, d_W5h);  half* pW5 = (half*)p;
    cudaGetSymbolAddress(&p, d_W1h);  half* pW1 = (half*)p;
    cudaGetSymbolAddress(&p, d_W2h);  half* pW2 = (half*)p;

    cudaFuncSetAttribute(qkvg_wmma,    cudaFuncAttributeMaxDynamicSharedMemorySize, SMEM_128);
    cudaFuncSetAttribute(ff1_wmma,     cudaFuncAttributeMaxDynamicSharedMemorySize, SMEM_128);
    cudaFuncSetAttribute(res_wmma<D>,  cudaFuncAttributeMaxDynamicSharedMemorySize, SMEM_64);
    cudaFuncSetAttribute(res_wmma<FF>, cudaFuncAttributeMaxDynamicSharedMemorySize, SMEM_64);

    init_tables_kernel<<<(S * 32 + 255) / 256, 256>>>();      // launch 1
    add_pos_kernel<<<(S * D + 255) / 256, 256>>>(x_in, pe);   // launch 2

    dim3 g5(DD / 256, 1, 20);
    wconv5_kernel<<<g5, 256>>>(Wq, Wk, Wv, Wg, Wo, pW5);      // launch 3
    dim3 g1((D * FF) / 256, 1, L);
    wconv_kernel<<<g1, 256>>>(W1, pW1, D * FF);               // launch 4

    dim3 grid_qkvg(D / 128, S / 128, 4);   // 256 blocks
    dim3 grid_ff1(FF / 128, S / 128);      // 256 blocks
    dim3 grid_res(D / 128, S / 64);        // 128 blocks
    dim3 grid_ret(NC, H);                  // 256 blocks

    for (int l = 0; l < L; l++) {
        layernorm_split<<<S, 256>>>(px, ln1w + l * D, ln1b + l * D, 1e-5f);  // launch 5 (l=0)

        qkvg_wmma<<<grid_qkvg, 512, SMEM_128>>>(pyh, pyl,                    // launch 6 (l=0): ncu target
            pW5 + (size_t)l * 5 * DD,
            bq + l * D, bk + l * D, bv + l * D, bg + l * D);

        if (l == 0)
            wconv_kernel<<<g1, 256>>>(W2, pW2, FF * D);   // deferred; first use is res<FF> below

        chunk_kv_kernel<<<grid_ret, 256>>>(pk, pv);
        scan_kernel<<<(H * DH * DH + 255) / 256, 256>>>();
        retn_kernel<<<grid_ret, 256>>>(pq, pk, pv);   // writes d_grh/d_grl (g*groupnorm fused)

        res_wmma<D><<<grid_res, 512, SMEM_64>>>(pgrh, pgrl,
            pW5 + ((size_t)l * 5 + 4) * DD, bo + l * D);

        layernorm_split<<<S, 256>>>(px, ln2w + l * D, ln2b + l * D, 1e-5f);
        ff1_wmma<<<grid_ff1, 512, SMEM_128>>>(pyh, pyl,
            pW1 + (size_t)l * D * FF, b1 + l * FF);
        res_wmma<FF><<<grid_res, 512, SMEM_64>>>(pffh, pffl,
            pW2 + (size_t)l * FF * D, b2 + l * D);
    }

    final_kernel<<<S, 64>>>(Wout, bout, out);
}

// round 17
// speedup vs baseline: 2.8244x; 1.2958x over previous
#include <cuda_runtime.h>
#include <cuda_fp16.h>
#include <mma.h>
#include <math.h>
#include <stdint.h>

using namespace nvcuda;

#define S 2048
#define D 512
#define H 8
#define DH 64
#define L 4
#define FF 2048
#define NC (S / 64)
#define DD (D * D)

// ---------------- scratch (static device globals; no allocation) ----------------
__device__ float d_x  [S * D];
__device__ float d_q  [S * D];
__device__ float d_k  [S * D];
__device__ float d_v  [S * D];
__device__ float d_g  [S * D];
__device__ float d_sin[S * (DH / 2)];
__device__ float d_cos[S * (DH / 2)];
__device__ float d_gpow[H * S];
__device__ float d_U[H * NC * DH * DH];
__device__ float d_M[H * NC * DH * DH];

// fp16 activations (single precision, no compensation)
__device__ __align__(16) half d_yh [S * D];
__device__ __align__(16) half d_grh[S * D];
__device__ __align__(16) half d_ffh[S * FF];

// single-fp16 weights, NATIVE [K][N] layout. slot l*5+t for {q,k,v,g,o}
__device__ __align__(16) half d_W5h[20 * DD];
__device__ __align__(16) half d_W1h[4 * D * FF];   // [D][FF]
__device__ __align__(16) half d_W2h[4 * FF * D];   // [FF][D]

// ---------------- helpers ----------------
__device__ __forceinline__ uint32_t smem_to_u32(const void* p) {
    uint32_t a;
    asm("{ .reg .u64 t; cvta.to.shared.u64 t, %1; cvt.u32.u64 %0, t; }" : "=r"(a) : "l"(p));
    return a;
}
__device__ __forceinline__ void cp16(uint32_t dst, const void* src) {
    asm volatile("cp.async.cg.shared.global [%0], [%1], 16;" :: "r"(dst), "l"(src));
}
#define CP_COMMIT() asm volatile("cp.async.commit_group;" ::: "memory")
#define CP_WAIT0()  asm volatile("cp.async.wait_group 0;" ::: "memory")
#define CP_WAIT1()  asm volatile("cp.async.wait_group 1;" ::: "memory")

// ---------------- setup tables ----------------
__global__ void init_tables_kernel() {
    int idx = blockIdx.x * blockDim.x + threadIdx.x;
    if (idx < S * (DH / 2)) {
        int s = idx / (DH / 2);
        int j = idx % (DH / 2);
        double theta = pow(10000.0, -(double)(2 * j) / (double)DH);
        double ang = (double)s * theta;
        d_sin[idx] = (float)sin(ang);
        d_cos[idx] = (float)cos(ang);
    }
    if (idx < H * S) {
        int h = idx / S;
        int dd = idx % S;
        double lg0 = log(1.0 / 32.0);
        double lg1 = log(1.0 / 512.0);
        double gamma = 1.0 - exp(lg0 + (lg1 - lg0) * (double)h / 7.0);
        d_gpow[idx] = (float)exp((double)dd * log(gamma));
    }
}

__global__ void add_pos_kernel(const float* __restrict__ x, const float* __restrict__ pe) {
    int i = blockIdx.x * blockDim.x + threadIdx.x;
    if (i < S * D) d_x[i] = x[i] + pe[i % D];
}

// ---------------- weight convert (single fp16, layout preserved) ----------------
__global__ void wconv5_kernel(const float* __restrict__ Wq, const float* __restrict__ Wk,
                              const float* __restrict__ Wv, const float* __restrict__ Wg,
                              const float* __restrict__ Wo, half* __restrict__ dh) {
    int z = blockIdx.z;               // 0..19 = l*5+t
    int l = z / 5, t = z % 5;
    const float* src = (t == 0) ? Wq : (t == 1) ? Wk : (t == 2) ? Wv : (t == 3) ? Wg : Wo;
    int i = blockIdx.x * blockDim.x + threadIdx.x;
    dh[(size_t)z * DD + i] = __float2half(src[(size_t)l * DD + i]);
}

__global__ void wconv_kernel(const float* __restrict__ src, half* __restrict__ dh, int n) {
    int z = blockIdx.z;
    int i = blockIdx.x * blockDim.x + threadIdx.x;
    if (i >= n) return;
    dh[(size_t)z * n + i] = __float2half(src[(size_t)z * n + i]);
}

// ---------------- layernorm -> fp16 ----------------
__global__ void layernorm_h(const float* __restrict__ in,
                            const float* __restrict__ w, const float* __restrict__ b,
                            float eps) {
    int row = blockIdx.x;
    int t = threadIdx.x;
    const float* xr = in + row * D;
    __shared__ float red[256];
    float v0 = xr[t];
    float v1 = xr[t + 256];
    red[t] = v0 + v1;
    __syncthreads();
    for (int o = 128; o > 0; o >>= 1) { if (t < o) red[t] += red[t + o]; __syncthreads(); }
    float mu = red[0] * (1.0f / D);
    __syncthreads();
    float a0 = v0 - mu, a1 = v1 - mu;
    red[t] = a0 * a0 + a1 * a1;
    __syncthreads();
    for (int o = 128; o > 0; o >>= 1) { if (t < o) red[t] += red[t + o]; __syncthreads(); }
    float rstd = rsqrtf(red[0] * (1.0f / D) + eps);
    d_yh[row * D + t]       = __float2half(a0 * rstd * w[t] + b[t]);
    d_yh[row * D + t + 256] = __float2half(a1 * rstd * w[t + 256] + b[t + 256]);
}

// ================= wmma fp16 GEMM core (single term) =============
// BM in {128, 64}, BN=128, BK=64, 512 threads, 16 warps as 4x4.
// 3-stage cp.async pipeline. smem buffer = A | B.
#define ASTRIDE 72
#define BSTRIDE 136

template <int BM> struct CoreCfg {
    static constexpr int A_BYTES = BM * ASTRIDE * 2;
    static constexpr int B_BYTES = 64 * BSTRIDE * 2;       // 17408
    static constexpr int OFF_B2  = A_BYTES;
    static constexpr int BUF = A_BYTES + B_BYTES;
    static constexpr int MF = BM / 64;
};

template <int KDIM, int NDIM, int BM>
__device__ __forceinline__ void issue_chunk(const half* __restrict__ A,
                                            const half* __restrict__ B,
                                            uint32_t bufbase, int row0, int col0,
                                            int kc, int tid) {
    using C = CoreCfg<BM>;
#pragma unroll
    for (int i = 0; i < BM / 64; i++) {
        int e = tid + i * 512;
        int r = e >> 3, c8 = (e & 7) * 8;
        uint32_t doff = (uint32_t)(r * ASTRIDE + c8) * 2;
        cp16(bufbase + doff, A + (size_t)(row0 + r) * KDIM + kc + c8);
    }
#pragma unroll
    for (int i = 0; i < 2; i++) {
        int e = tid + i * 512;
        int r = e >> 4, n8 = (e & 15) * 8;
        uint32_t doff = (uint32_t)(r * BSTRIDE + n8) * 2;
        cp16(bufbase + C::OFF_B2 + doff, B + (size_t)(kc + r) * NDIM + col0 + n8);
    }
    CP_COMMIT();
}

template <int KDIM, int NDIM, int BM>
__device__ __forceinline__ void wmma_core(const half* __restrict__ A,
                                          const half* __restrict__ B,
                                          char* smem, int row0, int col0) {
    using C = CoreCfg<BM>;
    constexpr int MF = C::MF;
    constexpr int NCH = KDIM / 64;
    const int tid = threadIdx.x;
    const int warp = tid >> 5;
    const int wr = (warp >> 2) * (16 * MF);
    const int wc = (warp & 3) * 32;
    const uint32_t sb = smem_to_u32(smem);

    wmma::fragment<wmma::accumulator, 16, 16, 16, float> acc[MF][2];
#pragma unroll
    for (int m = 0; m < MF; m++)
#pragma unroll
        for (int n = 0; n < 2; n++) wmma::fill_fragment(acc[m][n], 0.0f);

    issue_chunk<KDIM, NDIM, BM>(A, B, sb, row0, col0, 0, tid);
    if (NCH > 1)
        issue_chunk<KDIM, NDIM, BM>(A, B, sb + C::BUF, row0, col0, 64, tid);

    int buf = 0;
    for (int c = 0; c < NCH; c++) {
        if (c + 1 < NCH) { CP_WAIT1(); } else { CP_WAIT0(); }
        __syncthreads();
        if (c + 2 < NCH) {
            int nb = buf + 2; if (nb >= 3) nb -= 3;
            issue_chunk<KDIM, NDIM, BM>(A, B, sb + nb * C::BUF,
                                        row0, col0, (c + 2) * 64, tid);
        }

        const half* as = (const half*)(smem + buf * C::BUF);
        const half* bs = (const half*)(smem + buf * C::BUF + C::OFF_B2);

#pragma unroll
        for (int ks = 0; ks < 4; ks++) {
            wmma::fragment<wmma::matrix_a, 16, 16, 16, half, wmma::row_major> fa[MF];
            wmma::fragment<wmma::matrix_b, 16, 16, 16, half, wmma::row_major> fb[2];
#pragma unroll
            for (int m = 0; m < MF; m++)
                wmma::load_matrix_sync(fa[m], as + (wr + m * 16) * ASTRIDE + ks * 16, ASTRIDE);
#pragma unroll
            for (int n = 0; n < 2; n++)
                wmma::load_matrix_sync(fb[n], bs + (ks * 16) * BSTRIDE + wc + n * 16, BSTRIDE);
#pragma unroll
            for (int n = 0; n < 2; n++)
#pragma unroll
                for (int m = 0; m < MF; m++)
                    wmma::mma_sync(acc[m][n], fa[m], fb[n], acc[m][n]);
        }
        buf++; if (buf == 3) buf = 0;
    }

    // stage result into smem as f32 [BM][132]
    __syncthreads();
    float* stage = (float*)smem;
#pragma unroll
    for (int m = 0; m < MF; m++)
#pragma unroll
        for (int n = 0; n < 2; n++)
            wmma::store_matrix_sync(stage + (wr + m * 16) * 132 + wc + n * 16,
                                    acc[m][n], 132, wmma::mem_row_major);
    __syncthreads();
}

#define SMEM_128 (3 * CoreCfg<128>::BUF)   // 107520
#define SMEM_64  (3 * CoreCfg<64>::BUF)    // 79872

// ---- qkvg: z=0:q(rope*0.125) 1:k(rope) 2:v 3:g(silu); f32 outputs ----
__global__ void __launch_bounds__(512) qkvg_wmma(
    const half* __restrict__ A, const half* __restrict__ W5,
    const float* __restrict__ bq, const float* __restrict__ bk,
    const float* __restrict__ bv, const float* __restrict__ bg) {
    extern __shared__ char smem[];
    int tid = threadIdx.x;
    int z = blockIdx.z;
    int row0 = blockIdx.y * 128, col0 = blockIdx.x * 128;
    const half* B = W5 + (size_t)z * DD;
    const float* bias = (z == 0) ? bq : (z == 1) ? bk : (z == 2) ? bv : bg;
    float* out = (z == 0) ? d_q : (z == 1) ? d_k : (z == 2) ? d_v : d_g;

    wmma_core<D, D, 128>(A, B, smem, row0, col0);

    float (*st)[132] = (float (*)[132])smem;
    for (int i = tid; i < 4096; i += 512) {
        int r = i >> 5, c4 = (i & 31) * 4;
        int row = row0 + r, col = col0 + c4;
        float v0 = st[r][c4 + 0] + bias[col + 0];
        float v1 = st[r][c4 + 1] + bias[col + 1];
        float v2 = st[r][c4 + 2] + bias[col + 2];
        float v3 = st[r][c4 + 3] + bias[col + 3];
        float4 o;
        if (z <= 1) {
            int j = (col & 63) >> 1;
            float c0 = d_cos[row * 32 + j],     s0 = d_sin[row * 32 + j];
            float c1 = d_cos[row * 32 + j + 1], s1 = d_sin[row * 32 + j + 1];
            float sc = (z == 0) ? 0.125f : 1.0f;
            o.x = (v0 * c0 - v1 * s0) * sc;
            o.y = (v1 * c0 + v0 * s0) * sc;
            o.z = (v2 * c1 - v3 * s1) * sc;
            o.w = (v3 * c1 + v2 * s1) * sc;
        } else if (z == 2) {
            o = make_float4(v0, v1, v2, v3);
        } else {
            o.x = v0 / (1.0f + expf(-v0));
            o.y = v1 / (1.0f + expf(-v1));
            o.z = v2 / (1.0f + expf(-v2));
            o.w = v3 / (1.0f + expf(-v3));
        }
        *(float4*)&out[(size_t)row * D + col] = o;
    }
}

// ---- ffn1: SiLU -> fp16 ----
__global__ void __launch_bounds__(512) ff1_wmma(
    const half* __restrict__ A, const half* __restrict__ B,
    const float* __restrict__ bias) {
    extern __shared__ char smem[];
    int tid = threadIdx.x;
    int row0 = blockIdx.y * 128, col0 = blockIdx.x * 128;

    wmma_core<D, FF, 128>(A, B, smem, row0, col0);

    float (*st)[132] = (float (*)[132])smem;
    for (int i = tid; i < 4096; i += 512) {
        int r = i >> 5, c4 = (i & 31) * 4;
        int row = row0 + r, col = col0 + c4;
        size_t o = (size_t)row * FF + col;
#pragma unroll
        for (int j2 = 0; j2 < 4; j2++) {
            float t = st[r][c4 + j2] + bias[col + j2];
            d_ffh[o + j2] = __float2half(t / (1.0f + expf(-t)));
        }
    }
}

// ---- residual GEMM (BM=64): d_x += A@W + bias ----
template <int KDIM>
__global__ void __launch_bounds__(512) res_wmma(
    const half* __restrict__ A, const half* __restrict__ B,
    const float* __restrict__ bias) {
    extern __shared__ char smem[];
    int tid = threadIdx.x;
    int row0 = blockIdx.y * 64, col0 = blockIdx.x * 128;

    wmma_core<KDIM, D, 64>(A, B, smem, row0, col0);

    float (*st)[132] = (float (*)[132])smem;
    for (int i = tid; i < 2048; i += 512) {
        int r = i >> 5, c4 = (i & 31) * 4;
        int row = row0 + r, col = col0 + c4;
        float4 oldv = *(float4*)&d_x[(size_t)row * D + col];
        float4 o;
        o.x = st[r][c4 + 0] + bias[col + 0] + oldv.x;
        o.y = st[r][c4 + 1] + bias[col + 1] + oldv.y;
        o.z = st[r][c4 + 2] + bias[col + 2] + oldv.z;
        o.w = st[r][c4 + 3] + bias[col + 3] + oldv.w;
        *(float4*)&d_x[(size_t)row * D + col] = o;
    }
}

// ================= chunked retention =================
__global__ void chunk_kv_kernel(const float* __restrict__ k, const float* __restrict__ v) {
    __shared__ float ks[64][68];
    __shared__ float vs[64][68];
    int c = blockIdx.x, h = blockIdx.y;
    int s0 = c * 64;
    int tid = threadIdx.x;
    const float* gp = d_gpow + h * S;

    for (int i = tid; i < 64 * 16; i += 256) {
        int r = i >> 4;
        int c4 = (i & 15) * 4;
        float g = gp[63 - r];
        float4 kv = *(const float4*)&k[(s0 + r) * D + h * DH + c4];
        ks[r][c4 + 0] = kv.x * g; ks[r][c4 + 1] = kv.y * g;
        ks[r][c4 + 2] = kv.z * g; ks[r][c4 + 3] = kv.w * g;
        float4 vv = *(const float4*)&v[(s0 + r) * D + h * DH + c4];
        vs[r][c4 + 0] = vv.x; vs[r][c4 + 1] = vv.y;
        vs[r][c4 + 2] = vv.z; vs[r][c4 + 3] = vv.w;
    }
    __syncthreads();

    int tx = tid & 15, ty = tid >> 4;
    float acc[4][4] = {};
#pragma unroll 8
    for (int p = 0; p < 64; p++) {
        float4 a = *(const float4*)&ks[p][ty * 4];
        float4 b = *(const float4*)&vs[p][tx * 4];
        acc[0][0] += a.x * b.x; acc[0][1] += a.x * b.y; acc[0][2] += a.x * b.z; acc[0][3] += a.x * b.w;
        acc[1][0] += a.y * b.x; acc[1][1] += a.y * b.y; acc[1][2] += a.y * b.z; acc[1][3] += a.y * b.w;
        acc[2][0] += a.z * b.x; acc[2][1] += a.z * b.y; acc[2][2] += a.z * b.z; acc[2][3] += a.z * b.w;
        acc[3][0] += a.w * b.x; acc[3][1] += a.w * b.y; acc[3][2] += a.w * b.z; acc[3][3] += a.w * b.w;
    }
    float* U = d_U + (h * NC + c) * (DH * DH);
#pragma unroll
    for (int r = 0; r < 4; r++)
        *(float4*)&U[(ty * 4 + r) * DH + tx * 4] = make_float4(acc[r][0], acc[r][1], acc[r][2], acc[r][3]);
}

__global__ void scan_kernel() {
    int e = blockIdx.x * blockDim.x + threadIdx.x;
    if (e >= H * DH * DH) return;
    int h = e >> 12;
    int idx = e & 4095;
    float gc = d_gpow[h * S + 64];
    float m = 0.0f;
    for (int c = 0; c < NC; c++) {
        d_M[(h * NC + c) * 4096 + idx] = m;
        m = gc * m + d_U[(h * NC + c) * 4096 + idx];
    }
}

// retention + groupnorm + (g * ret) fp16 fused
__global__ void retn_kernel(const float* __restrict__ q, const float* __restrict__ k,
                            const float* __restrict__ v) {
    __shared__ float qs[64][65];
    __shared__ float ks[32][65];
    __shared__ float vs[32][65];
    __shared__ float ss[64][33];

    int h = blockIdx.y;
    int cidx = blockIdx.x;
    int s0 = cidx * 64;
    int tid = threadIdx.x;

    for (int i = tid; i < 64 * 16; i += 256) {
        int r = i >> 4;
        int c4 = (i & 15) * 4;
        float4 t = *(const float4*)&q[(s0 + r) * D + h * DH + c4];
        qs[r][c4 + 0] = t.x; qs[r][c4 + 1] = t.y; qs[r][c4 + 2] = t.z; qs[r][c4 + 3] = t.w;
    }

    int aty = tid >> 4, atx = tid & 15;
    int bty = tid >> 4, btx = tid & 15;
    float acc[4][4] = {};
    const float* gp = d_gpow + h * S;
    const float* Mh = d_M + (h * NC + cidx) * (DH * DH);
    __syncthreads();

    for (int t = 0; t < 2; t++) {
        int m0 = s0 + t * 32;
        for (int i = tid; i < 32 * 16; i += 256) {
            int r = i >> 4;
            int c4 = (i & 15) * 4;
            float4 kv = *(const float4*)&k[(m0 + r) * D + h * DH + c4];
            ks[r][c4 + 0] = kv.x; ks[r][c4 + 1] = kv.y; ks[r][c4 + 2] = kv.z; ks[r][c4 + 3] = kv.w;
            float4 vv = *(const float4*)&v[(m0 + r) * D + h * DH + c4];
            vs[r][c4 + 0] = vv.x; vs[r][c4 + 1] = vv.y; vs[r][c4 + 2] = vv.z; vs[r][c4 + 3] = vv.w;
        }
        __syncthreads();

        float sv[4][2] = {};
#pragma unroll 16
        for (int d = 0; d < 64; d++) {
            float qr0 = qs[aty * 4 + 0][d];
            float qr1 = qs[aty * 4 + 1][d];
            float qr2 = qs[aty * 4 + 2][d];
            float qr3 = qs[aty * 4 + 3][d];
            float kc0 = ks[atx * 2 + 0][d];
            float kc1 = ks[atx * 2 + 1][d];
            sv[0][0] += qr0 * kc0; sv[0][1] += qr0 * kc1;
            sv[1][0] += qr1 * kc0; sv[1][1] += qr1 * kc1;
            sv[2][0] += qr2 * kc0; sv[2][1] += qr2 * kc1;
            sv[3][0] += qr3 * kc0; sv[3][1] += qr3 * kc1;
        }
#pragma unroll
        for (int r = 0; r < 4; r++)
#pragma unroll
            for (int c = 0; c < 2; c++) {
                int qi = s0 + aty * 4 + r;
                int kj = m0 + atx * 2 + c;
                int dist = qi - kj;
                ss[aty * 4 + r][atx * 2 + c] = (dist >= 0) ? sv[r][c] * gp[dist] : 0.0f;
            }
        __syncthreads();

#pragma unroll 8
        for (int j = 0; j < 32; j++) {
            float vr0 = vs[j][btx * 4 + 0];
            float vr1 = vs[j][btx * 4 + 1];
            float vr2 = vs[j][btx * 4 + 2];
            float vr3 = vs[j][btx * 4 + 3];
            float s0r = ss[bty * 4 + 0][j];
            float s1r = ss[bty * 4 + 1][j];
            float s2r = ss[bty * 4 + 2][j];
            float s3r = ss[bty * 4 + 3][j];
            acc[0][0] += s0r * vr0; acc[0][1] += s0r * vr1; acc[0][2] += s0r * vr2; acc[0][3] += s0r * vr3;
            acc[1][0] += s1r * vr0; acc[1][1] += s1r * vr1; acc[1][2] += s1r * vr2; acc[1][3] += s1r * vr3;
            acc[2][0] += s2r * vr0; acc[2][1] += s2r * vr1; acc[2][2] += s2r * vr2; acc[2][3] += s2r * vr3;
            acc[3][0] += s3r * vr0; acc[3][1] += s3r * vr1; acc[3][2] += s3r * vr2; acc[3][3] += s3r * vr3;
        }
        __syncthreads();
    }

    if (cidx > 0) {
        for (int t2 = 0; t2 < 2; t2++) {
            for (int i = tid; i < 32 * 16; i += 256) {
                int r = i >> 4;
                int c4 = (i & 15) * 4;
                float4 mv = *(const float4*)&Mh[(t2 * 32 + r) * DH + c4];
                vs[r][c4 + 0] = mv.x; vs[r][c4 + 1] = mv.y; vs[r][c4 + 2] = mv.z; vs[r][c4 + 3] = mv.w;
            }
            for (int i = tid; i < 64 * 32; i += 256) {
                int r = i >> 5;
                int j = i & 31;
                ss[r][j] = qs[r][t2 * 32 + j] * gp[r + 1];
            }
            __syncthreads();
#pragma unroll 8
            for (int j = 0; j < 32; j++) {
                float vr0 = vs[j][btx * 4 + 0];
                float vr1 = vs[j][btx * 4 + 1];
                float vr2 = vs[j][btx * 4 + 2];
                float vr3 = vs[j][btx * 4 + 3];
                float s0r = ss[bty * 4 + 0][j];
                float s1r = ss[bty * 4 + 1][j];
                float s2r = ss[bty * 4 + 2][j];
                float s3r = ss[bty * 4 + 3][j];
                acc[0][0] += s0r * vr0; acc[0][1] += s0r * vr1; acc[0][2] += s0r * vr2; acc[0][3] += s0r * vr3;
                acc[1][0] += s1r * vr0; acc[1][1] += s1r * vr1; acc[1][2] += s1r * vr2; acc[1][3] += s1r * vr3;
                acc[2][0] += s2r * vr0; acc[2][1] += s2r * vr1; acc[2][2] += s2r * vr2; acc[2][3] += s2r * vr3;
                acc[3][0] += s3r * vr0; acc[3][1] += s3r * vr1; acc[3][2] += s3r * vr2; acc[3][3] += s3r * vr3;
            }
            __syncthreads();
        }
    }

#pragma unroll
    for (int r = 0; r < 4; r++)
#pragma unroll
        for (int c = 0; c < 4; c++)
            qs[bty * 4 + r][btx * 4 + c] = acc[r][c];
    __syncthreads();

    if (tid < 64) {
        int i = tid;
        float mu = 0.0f;
#pragma unroll 16
        for (int d = 0; d < 64; d++) mu += qs[i][d];
        mu *= (1.0f / 64.0f);
        float var = 0.0f;
#pragma unroll 16
        for (int d = 0; d < 64; d++) {
            float dd = qs[i][d] - mu;
            var += dd * dd;
        }
        var *= (1.0f / 64.0f);
        float rs = rsqrtf(var + 1e-6f);
        size_t base = (size_t)(s0 + i) * D + h * DH;
#pragma unroll 16
        for (int d = 0; d < 64; d++) {
            float gv = d_g[base + d] * ((qs[i][d] - mu) * rs);
            d_grh[base + d] = __float2half(gv);
        }
    }
}

// ---------------- final ----------------
__global__ void final_kernel(const float* __restrict__ Wout, const float* __restrict__ bout,
                             float* __restrict__ out) {
    int row = blockIdx.x;
    int t = threadIdx.x;
    float s = 0.0f;
    for (int i = t; i < D; i += 64) s += d_x[row * D + i] * Wout[i];
    __shared__ float red[64];
    red[t] = s;
    __syncthreads();
    for (int o = 32; o > 0; o >>= 1) {
        if (t < o) red[t] += red[t + o];
        __syncthreads();
    }
    if (t == 0) out[row] = 1.0f / (1.0f + expf(-(red[0] + bout[0])));
}

// ---------------- host orchestration ----------------
extern "C" void kernel_launch(void* const* d_in, const int* in_sizes, int n_in,
                              void* d_out, int out_size) {
    const float* x_in  = (const float*)d_in[0];
    const float* pe    = (const float*)d_in[1];
    const float* Wq    = (const float*)d_in[2];
    const float* bq    = (const float*)d_in[3];
    const float* Wk    = (const float*)d_in[4];
    const float* bk    = (const float*)d_in[5];
    const float* Wv    = (const float*)d_in[6];
    const float* bv    = (const float*)d_in[7];
    const float* Wg    = (const float*)d_in[8];
    const float* bg    = (const float*)d_in[9];
    const float* Wo    = (const float*)d_in[10];
    const float* bo    = (const float*)d_in[11];
    const float* ln1w  = (const float*)d_in[12];
    const float* ln1b  = (const float*)d_in[13];
    const float* ln2w  = (const float*)d_in[14];
    const float* ln2b  = (const float*)d_in[15];
    const float* W1    = (const float*)d_in[16];
    const float* b1    = (const float*)d_in[17];
    const float* W2    = (const float*)d_in[18];
    const float* b2    = (const float*)d_in[19];
    const float* Wout  = (const float*)d_in[20];
    const float* bout  = (const float*)d_in[21];
    float* out = (float*)d_out;

    void* p;
    cudaGetSymbolAddress(&p, d_x);    float* px = (float*)p;
    cudaGetSymbolAddress(&p, d_q);    float* pq = (float*)p;
    cudaGetSymbolAddress(&p, d_k);    float* pk = (float*)p;
    cudaGetSymbolAddress(&p, d_v);    float* pv = (float*)p;
    cudaGetSymbolAddress(&p, d_yh);   half* pyh = (half*)p;
    cudaGetSymbolAddress(&p, d_grh);  half* pgrh = (half*)p;
    cudaGetSymbolAddress(&p, d_ffh);  half* pffh = (half*)p;
    cudaGetSymbolAddress(&p, d_W5h);  half* pW5 = (half*)p;
    cudaGetSymbolAddress(&p, d_W1h);  half* pW1 = (half*)p;
    cudaGetSymbolAddress(&p, d_W2h);  half* pW2 = (half*)p;

    cudaFuncSetAttribute(qkvg_wmma,    cudaFuncAttributeMaxDynamicSharedMemorySize, SMEM_128);
    cudaFuncSetAttribute(ff1_wmma,     cudaFuncAttributeMaxDynamicSharedMemorySize, SMEM_128);
    cudaFuncSetAttribute(res_wmma<D>,  cudaFuncAttributeMaxDynamicSharedMemorySize, SMEM_64);
    cudaFuncSetAttribute(res_wmma<FF>, cudaFuncAttributeMaxDynamicSharedMemorySize, SMEM_64);

    init_tables_kernel<<<(S * 32 + 255) / 256, 256>>>();      // launch 1
    add_pos_kernel<<<(S * D + 255) / 256, 256>>>(x_in, pe);   // launch 2

    dim3 g5(DD / 256, 1, 20);
    wconv5_kernel<<<g5, 256>>>(Wq, Wk, Wv, Wg, Wo, pW5);      // launch 3
    dim3 g1((D * FF) / 256, 1, L);
    wconv_kernel<<<g1, 256>>>(W1, pW1, D * FF);               // launch 4

    dim3 grid_qkvg(D / 128, S / 128, 4);   // 256 blocks
    dim3 grid_ff1(FF / 128, S / 128);      // 256 blocks
    dim3 grid_res(D / 128, S / 64);        // 128 blocks
    dim3 grid_ret(NC, H);                  // 256 blocks

    for (int l = 0; l < L; l++) {
        layernorm_h<<<S, 256>>>(px, ln1w + l * D, ln1b + l * D, 1e-5f);  // launch 5 (l=0)

        qkvg_wmma<<<grid_qkvg, 512, SMEM_128>>>(pyh,                     // launch 6 (l=0): ncu target
            pW5 + (size_t)l * 5 * DD,
            bq + l * D, bk + l * D, bv + l * D, bg + l * D);

        if (l == 0)
            wconv_kernel<<<g1, 256>>>(W2, pW2, FF * D);   // deferred; first use is res<FF> below

        chunk_kv_kernel<<<grid_ret, 256>>>(pk, pv);
        scan_kernel<<<(H * DH * DH + 255) / 256, 256>>>();
        retn_kernel<<<grid_ret, 256>>>(pq, pk, pv);   // writes d_grh (g*groupnorm fused)

        res_wmma<D><<<grid_res, 512, SMEM_64>>>(pgrh,
            pW5 + ((size_t)l * 5 + 4) * DD, bo + l * D);

        layernorm_h<<<S, 256>>>(px, ln2w + l * D, ln2b + l * D, 1e-5f);
        ff1_wmma<<<grid_ff1, 512, SMEM_128>>>(pyh,
            pW1 + (size_t)l * D * FF, b1 + l * FF);
        res_wmma<FF><<<grid_res, 512, SMEM_64>>>(pffh,
            pW2 + (size_t)l * FF * D, b2 + l * D);
    }

    final_kernel<<<S, 64>>>(Wout, bout, out);
}